// round 14
// baseline (speedup 1.0000x reference)
#include <cuda_runtime.h>
#include <cuda_fp16.h>
#include <math.h>
#include <stdint.h>

// Problem constants (fixed by the dataset)
#define BB   2
#define LL   4096
#define HH   16
#define MM   64
#define DMODEL 1024
#define NROWS (BB*LL*HH)
#define DN    0.3535533905932738f
#define DIAGC 0.0625f
#define INVSQRTM 0.125f

#define CT   64
#define NC   (LL/CT)
#define NBH  (BB*HH)
#define MROWS (BB*LL)             // 8192

// ---------------------------------------------------------------------------
// scratch
// ---------------------------------------------------------------------------
__device__ float g_q[MROWS*DMODEL];                      // fp32 q projection
__device__ float g_k[MROWS*DMODEL];                      // fp32 k projection
__device__ float g_kmax[NBH];
__device__ float g_kpart[NBH*16];
__device__ float g_kv[NBH*NC*MM*MM];
__device__ float g_ks[NBH*NC*MM];
__device__ __align__(16) __half g_xh[3*MROWS*DMODEL];    // fp16 inputs
__device__ __align__(16) __half g_vh[MROWS*DMODEL];      // fp16 v projection
__device__ __align__(16) __half g_qf[MROWS*DMODEL];      // fp16 phi(q)
__device__ __align__(16) __half g_kf[MROWS*DMODEL];      // fp16 phi(k)
__device__ __align__(16) __half g_oh[MROWS*DMODEL];      // fp16 attn output
__device__ __align__(16) __half g_wh[4*DMODEL*DMODEL];   // transposed fp16 weights

// ---------------------------------------------------------------------------
// helpers
// ---------------------------------------------------------------------------
__device__ __forceinline__ uint32_t smem_to_u32(const void* p) {
    uint32_t a;
    asm("{ .reg .u64 t; cvta.to.shared.u64 t, %1; cvt.u32.u64 %0, t; }"
        : "=r"(a) : "l"(p));
    return a;
}
#define SWZ64(b) ((b) ^ (((b) >> 3) & 0x30))
#define SWZ128(b) ((b) ^ (((b) >> 3) & 0x70))

__device__ __forceinline__ void cp16(uint32_t dst, const void* src) {
    asm volatile("cp.async.cg.shared.global [%0], [%1], 16;" :: "r"(dst), "l"(src));
}
__device__ __forceinline__ void cp_commit() {
    asm volatile("cp.async.commit_group;" ::: "memory");
}
template<int N> __device__ __forceinline__ void cp_wait() {
    asm volatile("cp.async.wait_group %0;" :: "n"(N) : "memory");
}
__device__ __forceinline__ void ldsm4(uint32_t (&r)[4], uint32_t addr) {
    asm volatile("ldmatrix.sync.aligned.m8n8.x4.shared.b16 {%0,%1,%2,%3}, [%4];"
        : "=r"(r[0]), "=r"(r[1]), "=r"(r[2]), "=r"(r[3]) : "r"(addr));
}
__device__ __forceinline__ void mma_f16(float (&d)[4], const uint32_t (&a)[4],
                                        const uint32_t* b) {
    asm volatile("mma.sync.aligned.m16n8k16.row.col.f32.f16.f16.f32 "
        "{%0,%1,%2,%3}, {%4,%5,%6,%7}, {%8,%9}, {%0,%1,%2,%3};"
        : "+f"(d[0]), "+f"(d[1]), "+f"(d[2]), "+f"(d[3])
        : "r"(a[0]), "r"(a[1]), "r"(a[2]), "r"(a[3]), "r"(b[0]), "r"(b[1]));
}
// fast exp on the FMA pipe. rel err ~2.4e-6.
__device__ __forceinline__ float fast_exp(float x) {
    float y = fmaxf(x * 1.4426950408889634f, -120.f);
    float n = rintf(y);
    float t = (y - n) * 0.6931471805599453f;
    float p = 1.f + t * (1.f + t * (0.5f + t * (0.16666667f
              + t * (0.041666667f + t * 0.0083333333f))));
    return p * __int_as_float(((int)n + 127) << 23);
}

// ---------------------------------------------------------------------------
// fp16 HMMA GEMM (batched over grid.z): C = A[8192,1024] @ B^T + bias
// ---------------------------------------------------------------------------
#define GM_TILE  8192
#define GM_STAGE (2*GM_TILE)
#define GM_NSTG  3
#define GM_SMEM  (GM_NSTG*GM_STAGE)     // 48KB
#define GM_NKC   32

struct GemmBatch {
    const __half *A[3], *B[3];
    const float* bias[3];
    void* C[3];
    int hout[3];
};

__device__ __forceinline__ void gm_cp_chunk(
    uint32_t stage, const __half* A, const __half* B,
    int bm, int bn, int kc, int r_lo, int cb)
{
    const size_t ko = (size_t)kc * 64 + cb;
#pragma unroll
    for (int j = 0; j < 2; j++) {
        const int row = r_lo + 64 * j;
        const uint32_t swz = SWZ64((uint32_t)(row * 64 + cb));
        cp16(stage + swz,           (const char*)A + (size_t)(bm + row) * 2048 + ko);
        cp16(stage + GM_TILE + swz, (const char*)B + (size_t)(bn + row) * 2048 + ko);
    }
    cp_commit();
}

__device__ __forceinline__ void gm_compute(uint32_t st, int wm, int wn, int lid,
                                           float acc[2][8][4])
{
    const int ar  = wm + (lid & 15);
    const int akb = (lid >> 4) * 16;
    const int br  = (lid & 7) + ((lid >> 4) << 3);
    const int bkb = ((lid >> 3) & 1) * 16;
#pragma unroll
    for (int k0 = 0; k0 < 2; k0++) {
        const int kb = k0 * 32;
        uint32_t ah[2][4];
        ldsm4(ah[0], st + SWZ64((uint32_t)(ar * 64 + kb + akb)));
        ldsm4(ah[1], st + SWZ64((uint32_t)((ar + 16) * 64 + kb + akb)));
        uint32_t bh[4][4];
#pragma unroll
        for (int g = 0; g < 4; g++)
            ldsm4(bh[g], st + GM_TILE +
                  SWZ64((uint32_t)((wn + g * 16 + br) * 64 + kb + bkb)));
#pragma unroll
        for (int mt = 0; mt < 2; mt++)
#pragma unroll
            for (int g = 0; g < 4; g++) {
                mma_f16(acc[mt][2 * g],     ah[mt], &bh[g][0]);
                mma_f16(acc[mt][2 * g + 1], ah[mt], &bh[g][2]);
            }
    }
}

__global__ __launch_bounds__(256, 2)
void gemm_f16(GemmBatch batch)
{
    extern __shared__ char smem[];
    const uint32_t sb = smem_to_u32(smem);
    const int tid = threadIdx.x;
    const int wid = tid >> 5, lid = tid & 31;
    const int gz = blockIdx.z;
    const __half* A = batch.A[gz];
    const __half* B = batch.B[gz];
    const float* bias = batch.bias[gz];

    const int bn = blockIdx.x * 128;
    const int bm = blockIdx.y * 128;
    const int r_lo = tid >> 2;
    const int cb = (tid & 3) * 16;
    const int wm = (wid & 3) * 32;
    const int wn = (wid >> 2) * 64;

    float acc[2][8][4];
#pragma unroll
    for (int mt = 0; mt < 2; mt++)
#pragma unroll
        for (int nt = 0; nt < 8; nt++)
#pragma unroll
            for (int j = 0; j < 4; j++) acc[mt][nt][j] = 0.f;

    gm_cp_chunk(sb + 0 * GM_STAGE, A, B, bm, bn, 0, r_lo, cb);
    gm_cp_chunk(sb + 1 * GM_STAGE, A, B, bm, bn, 1, r_lo, cb);

    uint32_t st_cur = sb;
    uint32_t st_nxt = sb + GM_STAGE;
    uint32_t st_fill = sb + 2 * GM_STAGE;
    for (int i = 0; i < GM_NKC; i++) {
        if (i == GM_NKC - 1) cp_wait<0>(); else cp_wait<1>();
        __syncthreads();
        if (i + 2 < GM_NKC)
            gm_cp_chunk(st_fill, A, B, bm, bn, i + 2, r_lo, cb);
        gm_compute(st_cur, wm, wn, lid, acc);
        uint32_t t = st_cur;
        st_cur = st_nxt; st_nxt = st_fill; st_fill = t;
    }

    const int row_b = bm + wm + (lid >> 2);
    const int col_b = bn + wn + (lid & 3) * 2;
    if (batch.hout[gz]) {
        __half* C = (__half*)batch.C[gz];
#pragma unroll
        for (int mt = 0; mt < 2; mt++) {
#pragma unroll
            for (int nt = 0; nt < 8; nt++) {
                const int col = col_b + nt * 8;
                const float b0 = bias[col], b1 = bias[col + 1];
                const int r0 = row_b + mt * 16;
                *(__half2*)&C[(size_t)r0 * DMODEL + col] =
                    __floats2half2_rn(acc[mt][nt][0] + b0, acc[mt][nt][1] + b1);
                *(__half2*)&C[(size_t)(r0 + 8) * DMODEL + col] =
                    __floats2half2_rn(acc[mt][nt][2] + b0, acc[mt][nt][3] + b1);
            }
        }
    } else {
        float* C = (float*)batch.C[gz];
#pragma unroll
        for (int mt = 0; mt < 2; mt++) {
#pragma unroll
            for (int nt = 0; nt < 8; nt++) {
                const int col = col_b + nt * 8;
                const float b0 = bias[col], b1 = bias[col + 1];
                const int r0 = row_b + mt * 16;
                float2 v0, v1;
                v0.x = acc[mt][nt][0] + b0; v0.y = acc[mt][nt][1] + b1;
                v1.x = acc[mt][nt][2] + b0; v1.y = acc[mt][nt][3] + b1;
                *(float2*)&C[(size_t)r0 * DMODEL + col] = v0;
                *(float2*)&C[(size_t)(r0 + 8) * DMODEL + col] = v1;
            }
        }
    }
}

// ---------------------------------------------------------------------------
// fp32 -> fp16 conversion pass (batched over grid.y)
// ---------------------------------------------------------------------------
struct CvtBatch { const float* x[3]; __half* h[3]; };

__global__ __launch_bounds__(256)
void cvt_f16_kernel(CvtBatch batch)
{
    const float* x = batch.x[blockIdx.y];
    __half* h = batch.h[blockIdx.y];
    const int i = (blockIdx.x * 256 + threadIdx.x) * 4;
    float4 v = *(const float4*)(x + i);
    __half2* p = (__half2*)(h + i);
    p[0] = __floats2half2_rn(v.x, v.y);
    p[1] = __floats2half2_rn(v.z, v.w);
}

// ---------------------------------------------------------------------------
// weight transpose + fp16 round (batched over grid.z, up to 2 per launch)
// ---------------------------------------------------------------------------
struct WtBatch { const float* W[2]; __half* T[2]; };

__global__ __launch_bounds__(256)
void wt_cvt_kernel(WtBatch batch)
{
    __shared__ float t[32][33];
    const float* W = batch.W[blockIdx.z];
    __half* T = batch.T[blockIdx.z];
    const int kx = blockIdx.x * 32;
    const int nx = blockIdx.y * 32;
    const int tx = threadIdx.x & 31, ty = threadIdx.x >> 5;
    for (int r = ty; r < 32; r += 8)
        t[r][tx] = W[(size_t)(kx + r) * DMODEL + nx + tx];
    __syncthreads();
    for (int r = ty; r < 32; r += 8)
        T[(size_t)(nx + r) * DMODEL + kx + tx] = __float2half_rn(t[tx][r]);
}

// ---------------------------------------------------------------------------
// kmax (two stage)
// ---------------------------------------------------------------------------
__global__ void kmax_part_kernel(const float* __restrict__ Kp, float* __restrict__ kpart)
{
    const int bh = blockIdx.y, sl = blockIdx.x;
    const int b = bh >> 4, h = bh & 15;
    const int tid = threadIdx.x;
    float m = -1e30f;
    const int l0 = sl * 256;
    for (int idx = tid; idx < 256 * MM; idx += 256) {
        int l = l0 + (idx >> 6), mm = idx & 63;
        m = fmaxf(m, Kp[((size_t)(b * LL + l) * HH + h) * MM + mm]);
    }
    __shared__ float red[256];
    red[tid] = m;
    __syncthreads();
    for (int s = 128; s > 0; s >>= 1) {
        if (tid < s) red[tid] = fmaxf(red[tid], red[tid + s]);
        __syncthreads();
    }
    if (tid == 0) kpart[bh * 16 + sl] = red[0];
}

__global__ void kmax_final_kernel(const float* __restrict__ kpart, float* __restrict__ kmax)
{
    const int bh = blockIdx.x;
    const int t = threadIdx.x;
    __shared__ float red[16];
    red[t] = kpart[bh * 16 + t];
    __syncthreads();
    if (t < 8) red[t] = fmaxf(red[t], red[t + 8]);
    __syncthreads();
    if (t < 4) red[t] = fmaxf(red[t], red[t + 4]);
    __syncthreads();
    if (t == 0) kmax[bh] = DN * fmaxf(fmaxf(red[0], red[1]), fmaxf(red[2], red[3]));
}

// ---------------------------------------------------------------------------
// FAVOR feature map: fp32 in -> fp16 phi out. grid.y: 0=query, 1=key.
// ---------------------------------------------------------------------------
#define FV_P 68
__global__ __launch_bounds__(256)
void favor_kernel(const float* __restrict__ Xq, const float* __restrict__ Xk,
                  __half* __restrict__ Oq, __half* __restrict__ Ok,
                  const float* __restrict__ Wfq, const float* __restrict__ Wfk,
                  const float* __restrict__ kmax)
{
    __shared__ float Wt[64 * FV_P];
    __shared__ float xst[64 * FV_P];
    __shared__ float rowss[64];
    __shared__ float rowmx[64];

    const int is_query = (blockIdx.y == 0);
    const float* X = is_query ? Xq : Xk;
    __half* O = is_query ? Oq : Ok;
    const float* Wf = is_query ? Wfq : Wfk;
    const int tid = threadIdx.x;
    const int row0 = blockIdx.x * 64;

    for (int i = tid; i < 64 * 64; i += 256) {
        int d = i >> 6, m = i & 63;
        Wt[m * FV_P + d] = Wf[i];
    }
    {
        const int r = tid >> 2;
        const int m0 = (tid & 3) * 16;
        const float* src = X + (size_t)(row0 + r) * 64 + m0;
#pragma unroll
        for (int j4 = 0; j4 < 4; j4++) {
            float4 v = *(const float4*)(src + j4 * 4);
            int m = m0 + j4 * 4;
            xst[(m + 0) * FV_P + r] = DN * v.x;
            xst[(m + 1) * FV_P + r] = DN * v.y;
            xst[(m + 2) * FV_P + r] = DN * v.z;
            xst[(m + 3) * FV_P + r] = DN * v.w;
        }
    }
    __syncthreads();

    if (tid < 64) {
        float ss = 0.f, mx = -1e30f;
        for (int m = 0; m < 64; m++) {
            float x = xst[m * FV_P + tid];
            ss = fmaf(x, x, ss);
            mx = fmaxf(mx, x);
        }
        rowss[tid] = ss;
        rowmx[tid] = mx;
    }
    __syncthreads();

    const int tx = tid & 15, ty = tid >> 4;
    const int d0 = tx * 4, r0 = ty * 4;
    float acc[4][4];
#pragma unroll
    for (int i = 0; i < 4; i++)
#pragma unroll
        for (int j = 0; j < 4; j++) acc[i][j] = 0.f;

    for (int m = 0; m < 64; m++) {
        float4 w4 = *(float4*)&Wt[m * FV_P + d0];
        float4 x4 = *(float4*)&xst[m * FV_P + r0];
        float wf[4] = {w4.x, w4.y, w4.z, w4.w};
        float xf[4] = {x4.x, x4.y, x4.z, x4.w};
#pragma unroll
        for (int i = 0; i < 4; i++)
#pragma unroll
            for (int j = 0; j < 4; j++)
                acc[i][j] = fmaf(xf[i], wf[j], acc[i][j]);
    }

#pragma unroll
    for (int i = 0; i < 4; i++) {
        const int r = r0 + i;
        const int row = row0 + r;
        float mq;
        if (is_query) mq = rowmx[r];
        else          mq = kmax[((row >> 16) << 4) + (row & 15)];
        const float base = -DIAGC * rowss[r] - mq + 1e-8f;
        __half* dst = O + (size_t)row * 64 + d0;
        *(__half2*)dst = __floats2half2_rn(
            INVSQRTM * fast_exp(acc[i][0] + base),
            INVSQRTM * fast_exp(acc[i][1] + base));
        *(__half2*)(dst + 2) = __floats2half2_rn(
            INVSQRTM * fast_exp(acc[i][2] + base),
            INVSQRTM * fast_exp(acc[i][3] + base));
    }
}

// ---------------------------------------------------------------------------
// chunk_sum (HMMA): KV[m][d] = sum_c k[c][m] * v[c][d]; ksum[m] = sum_c k[c][m]
// Stage Kt[m][c], Vt[d][c] transposed (128B rows, SW128); gemm-style loads.
// ---------------------------------------------------------------------------
__global__ __launch_bounds__(256)
void chunk_sum_kernel(const __half* __restrict__ Kf, const __half* __restrict__ Vh,
                      float* __restrict__ kv, float* __restrict__ ks)
{
    __shared__ __align__(128) char sKt[8192];
    __shared__ __align__(128) char sVt[8192];
    const uint32_t ktb = smem_to_u32(sKt);
    const uint32_t vtb = smem_to_u32(sVt);

    const int c  = blockIdx.x;
    const int bh = blockIdx.y;
    const int b = bh >> 4, h = bh & 15;
    const int tid = threadIdx.x;
    const int wid = tid >> 5, lid = tid & 31;
    const size_t base = ((size_t)(b * LL + c * CT) * HH + h) * MM;
    const size_t stride = HH * MM;

    // transposed staging
    {
        const int cc = tid & 63, x0 = (tid >> 6) * 16;
        const __half* ksrc = Kf + base + (size_t)cc * stride + x0;
        const __half* vsrc = Vh + base + (size_t)cc * stride + x0;
#pragma unroll
        for (int j = 0; j < 16; j++) {
            *(__half*)(sKt + SWZ128((uint32_t)((x0 + j) * 128 + cc * 2))) = ksrc[j];
            *(__half*)(sVt + SWZ128((uint32_t)((x0 + j) * 128 + cc * 2))) = vsrc[j];
        }
    }
    __syncthreads();

    const int wm = (wid & 3) * 16;
    const int wn = (wid >> 2) * 32;
    const int a_ro = (lid & 15);
    const int a_kb = (lid >> 4) * 16;
    const int b_ro = (lid & 7) + ((lid >> 4) << 3);
    const int b_kb = ((lid >> 3) & 1) * 16;

    float acc[4][4];
#pragma unroll
    for (int nt = 0; nt < 4; nt++)
#pragma unroll
        for (int j = 0; j < 4; j++) acc[nt][j] = 0.f;

#pragma unroll
    for (int ksn = 0; ksn < 4; ksn++) {
        const int kb = ksn * 32;
        uint32_t aa[4], b0[4], b1[4];
        ldsm4(aa, ktb + SWZ128((uint32_t)((wm + a_ro) * 128 + kb + a_kb)));
        ldsm4(b0, vtb + SWZ128((uint32_t)((wn + b_ro) * 128 + kb + b_kb)));
        ldsm4(b1, vtb + SWZ128((uint32_t)((wn + 16 + b_ro) * 128 + kb + b_kb)));
        mma_f16(acc[0], aa, &b0[0]);
        mma_f16(acc[1], aa, &b0[2]);
        mma_f16(acc[2], aa, &b1[0]);
        mma_f16(acc[3], aa, &b1[2]);
    }

    float* out = kv + (size_t)(bh * NC + c) * MM * MM;
    const int fr = wm + (lid >> 2);
    const int fc = wn + (lid & 3) * 2;
#pragma unroll
    for (int nt = 0; nt < 4; nt++) {
        const int cc = fc + nt * 8;
        float2 lo, hi;
        lo.x = acc[nt][0]; lo.y = acc[nt][1];
        hi.x = acc[nt][2]; hi.y = acc[nt][3];
        *(float2*)&out[fr * 64 + cc] = lo;
        *(float2*)&out[(fr + 8) * 64 + cc] = hi;
    }

    if (tid < 64) {
        float s = 0.f;
        for (int cc = 0; cc < 64; cc++)
            s += __half2float(*(__half*)(sKt + SWZ128((uint32_t)(tid * 128 + cc * 2))));
        ks[(size_t)(bh * NC + c) * MM + tid] = s;
    }
}

// ---------------------------------------------------------------------------
// prefix over chunks
// ---------------------------------------------------------------------------
__global__ __launch_bounds__(256)
void prefix_kernel(float* __restrict__ kv, float* __restrict__ ks)
{
    const int dg = blockIdx.x;
    const int bh = blockIdx.y;
    const int tid = threadIdx.x;
    const int m = tid >> 2;
    const int d = dg * 16 + (tid & 3) * 4;
    float4 run = make_float4(0.f, 0.f, 0.f, 0.f);
    for (int c = 0; c < NC; c++) {
        float* p = kv + ((size_t)(bh * NC + c) * MM + m) * MM + d;
        float4 val = *(float4*)p;
        *(float4*)p = run;
        run.x += val.x; run.y += val.y; run.z += val.z; run.w += val.w;
    }
    if (dg == 0 && tid < 64) {
        float r = 0.f;
        for (int c = 0; c < NC; c++) {
            float* p = ks + (size_t)(bh * NC + c) * MM + tid;
            float v = *p;
            *p = r;
            r += v;
        }
    }
}

// ---------------------------------------------------------------------------
// chunk_attn (HMMA QK^T + AV; scalar fp32 Q*Sp): writes fp16 output
// smem layout (bytes): Qs 0, Ks 8192, Vt 16384, As 24576, Qt 32768 (9216),
//   Sp 41984 (17408), Os 59392 (17408), zpre 76800 (256), den 77056 (256)
// ---------------------------------------------------------------------------
#define CA_SMEM 77312
__global__ __launch_bounds__(256)
void chunk_attn_kernel(const __half* __restrict__ Qf, const __half* __restrict__ Kf,
                       const __half* __restrict__ Vh, const float* __restrict__ kv,
                       const float* __restrict__ ksum, __half* __restrict__ Out)
{
    extern __shared__ char smc[];
    const uint32_t sb = smem_to_u32(smc);
    __half* Qt  = (__half*)(smc + 32768);
    float* Sp   = (float*)(smc + 41984);
    float* Os   = (float*)(smc + 59392);
    float* zpre = (float*)(smc + 76800);
    float* den  = (float*)(smc + 77056);

    const int c  = blockIdx.x;
    const int bh = blockIdx.y;
    const int b = bh >> 4, h = bh & 15;
    const int tid = threadIdx.x;
    const int wid = tid >> 5, lid = tid & 31;
    const size_t base = ((size_t)(b * LL + c * CT) * HH + h) * MM;
    const size_t stride = HH * MM;

    // --- staging ---
    {   // Qs[r][m], Ks[c][m] row-major SW128
        const int r = tid >> 2, m0 = (tid & 3) * 16;
        const __half* qsrc = Qf + base + (size_t)r * stride + m0;
        const __half* ksrc = Kf + base + (size_t)r * stride + m0;
        const uint32_t o0 = SWZ128((uint32_t)(r * 128 + m0 * 2));
        const uint32_t o1 = SWZ128((uint32_t)(r * 128 + m0 * 2 + 16));
        *(uint4*)(smc + o0) = *(const uint4*)qsrc;
        *(uint4*)(smc + o1) = *(const uint4*)(qsrc + 8);
        *(uint4*)(smc + 8192 + o0) = *(const uint4*)ksrc;
        *(uint4*)(smc + 8192 + o1) = *(const uint4*)(ksrc + 8);
    }
    {   // Vt[d][c] transposed SW128; Qt[m][r] transposed (pad 72)
        const int cc = tid & 63, x0 = (tid >> 6) * 16;
        const __half* vsrc = Vh + base + (size_t)cc * stride + x0;
        const __half* qsrc = Qf + base + (size_t)cc * stride + x0;
#pragma unroll
        for (int j = 0; j < 16; j++) {
            *(__half*)(smc + 16384 + SWZ128((uint32_t)((x0 + j) * 128 + cc * 2))) = vsrc[j];
            Qt[(x0 + j) * 72 + cc] = qsrc[j];
        }
    }
    for (int i = tid; i < 64 * 16; i += 256) {
        int m = i >> 4, d4 = (i & 15) * 4;
        *(float4*)&Sp[m * 68 + d4] =
            *(const float4*)&kv[((size_t)(bh * NC + c) * MM + m) * MM + d4];
    }
    if (tid < 64) {
        zpre[tid] = ksum[(size_t)(bh * NC + c) * MM + tid];
        den[tid] = 0.f;
    }
    __syncthreads();

    const int wm = (wid & 3) * 16;
    const int wn = (wid >> 2) * 32;
    const int a_ro = (lid & 15);
    const int a_kb = (lid >> 4) * 16;
    const int b_ro = (lid & 7) + ((lid >> 4) << 3);
    const int b_kb = ((lid >> 3) & 1) * 16;

    // --- QK^T (A=Qs rows r, B=Ks rows c) ---
    float a[4][4];
#pragma unroll
    for (int nt = 0; nt < 4; nt++)
#pragma unroll
        for (int j = 0; j < 4; j++) a[nt][j] = 0.f;
#pragma unroll
    for (int ksn = 0; ksn < 4; ksn++) {
        const int kb = ksn * 32;
        uint32_t aa[4], b0[4], b1[4];
        ldsm4(aa, sb + SWZ128((uint32_t)((wm + a_ro) * 128 + kb + a_kb)));
        ldsm4(b0, sb + 8192 + SWZ128((uint32_t)((wn + b_ro) * 128 + kb + b_kb)));
        ldsm4(b1, sb + 8192 + SWZ128((uint32_t)((wn + 16 + b_ro) * 128 + kb + b_kb)));
        mma_f16(a[0], aa, &b0[0]);
        mma_f16(a[1], aa, &b0[2]);
        mma_f16(a[2], aa, &b1[0]);
        mma_f16(a[3], aa, &b1[2]);
    }
    // mask (causal, local indices), store As[r][c] fp16, rowsum to den
    const int fr = wm + (lid >> 2);
    const int fcb = wn + (lid & 3) * 2;
    {
        float rs_lo = 0.f, rs_hi = 0.f;
#pragma unroll
        for (int nt = 0; nt < 4; nt++) {
            const int c0 = fcb + nt * 8;
            float v00 = (c0     <= fr)     ? a[nt][0] : 0.f;
            float v01 = (c0 + 1 <= fr)     ? a[nt][1] : 0.f;
            float v10 = (c0     <= fr + 8) ? a[nt][2] : 0.f;
            float v11 = (c0 + 1 <= fr + 8) ? a[nt][3] : 0.f;
            rs_lo += v00 + v01;
            rs_hi += v10 + v11;
            *(__half2*)(smc + 24576 + SWZ128((uint32_t)(fr * 128 + c0 * 2))) =
                __floats2half2_rn(v00, v01);
            *(__half2*)(smc + 24576 + SWZ128((uint32_t)((fr + 8) * 128 + c0 * 2))) =
                __floats2half2_rn(v10, v11);
        }
        atomicAdd(&den[fr], rs_lo);
        atomicAdd(&den[fr + 8], rs_hi);
    }
    __syncthreads();

    // den += Q . zpre
    if (tid < 64) {
        float s = den[tid];
        for (int m = 0; m < 64; m++)
            s = fmaf(__half2float(Qt[m * 72 + tid]), zpre[m], s);
        den[tid] = s;
    }

    // --- AV (A=As rows r k=c, B=Vt rows d k=c) ---
    float o[4][4];
#pragma unroll
    for (int nt = 0; nt < 4; nt++)
#pragma unroll
        for (int j = 0; j < 4; j++) o[nt][j] = 0.f;
#pragma unroll
    for (int ksn = 0; ksn < 4; ksn++) {
        const int kb = ksn * 32;
        uint32_t aa[4], b0[4], b1[4];
        ldsm4(aa, sb + 24576 + SWZ128((uint32_t)((wm + a_ro) * 128 + kb + a_kb)));
        ldsm4(b0, sb + 16384 + SWZ128((uint32_t)((wn + b_ro) * 128 + kb + b_kb)));
        ldsm4(b1, sb + 16384 + SWZ128((uint32_t)((wn + 16 + b_ro) * 128 + kb + b_kb)));
        mma_f16(o[0], aa, &b0[0]);
        mma_f16(o[1], aa, &b0[2]);
        mma_f16(o[2], aa, &b1[0]);
        mma_f16(o[3], aa, &b1[2]);
    }
#pragma unroll
    for (int nt = 0; nt < 4; nt++) {
        const int c0 = fcb + nt * 8;
        float2 lo, hi;
        lo.x = o[nt][0]; lo.y = o[nt][1];
        hi.x = o[nt][2]; hi.y = o[nt][3];
        *(float2*)&Os[fr * 68 + c0] = lo;
        *(float2*)&Os[(fr + 8) * 68 + c0] = hi;
    }
    __syncthreads();

    // --- final: Q*Sp (scalar fp32) + Os, divide, store fp16 ---
    const int tx = tid & 15, ty = tid >> 4;
    const int r0 = ty * 4, d0 = tx * 4;
    float q_acc[4][4];
#pragma unroll
    for (int i = 0; i < 4; i++)
#pragma unroll
        for (int j = 0; j < 4; j++) q_acc[i][j] = 0.f;
    for (int m = 0; m < 64; m++) {
        float2 q01 = __half22float2(*(__half2*)&Qt[m * 72 + r0]);
        float2 q23 = __half22float2(*(__half2*)&Qt[m * 72 + r0 + 2]);
        float4 sv = *(float4*)&Sp[m * 68 + d0];
        float qf[4] = {q01.x, q01.y, q23.x, q23.y};
        float sf[4] = {sv.x, sv.y, sv.z, sv.w};
#pragma unroll
        for (int i = 0; i < 4; i++)
#pragma unroll
            for (int j = 0; j < 4; j++)
                q_acc[i][j] = fmaf(qf[i], sf[j], q_acc[i][j]);
    }
#pragma unroll
    for (int i = 0; i < 4; i++) {
        const float dinv = 1.f / den[r0 + i];
        const size_t idx = base + (size_t)(r0 + i) * stride + d0;
        float v0 = (q_acc[i][0] + Os[(r0 + i) * 68 + d0 + 0]) * dinv;
        float v1 = (q_acc[i][1] + Os[(r0 + i) * 68 + d0 + 1]) * dinv;
        float v2 = (q_acc[i][2] + Os[(r0 + i) * 68 + d0 + 2]) * dinv;
        float v3 = (q_acc[i][3] + Os[(r0 + i) * 68 + d0 + 3]) * dinv;
        __half2* p = (__half2*)(Out + idx);
        p[0] = __floats2half2_rn(v0, v1);
        p[1] = __floats2half2_rn(v2, v3);
    }
}

// ---------------------------------------------------------------------------
// Launch
// ---------------------------------------------------------------------------
extern "C" void kernel_launch(void* const* d_in, const int* in_sizes, int n_in,
                              void* d_out, int out_size)
{
    const float* queries = (const float*)d_in[0];
    const float* keys    = (const float*)d_in[1];
    const float* values  = (const float*)d_in[2];
    const float* Wq = (const float*)d_in[3];
    const float* bq = (const float*)d_in[4];
    const float* Wk = (const float*)d_in[5];
    const float* bk = (const float*)d_in[6];
    const float* Wv = (const float*)d_in[7];
    const float* bv = (const float*)d_in[8];
    const float* Wo = (const float*)d_in[9];
    const float* bo = (const float*)d_in[10];
    const float* Wfq = (const float*)d_in[11];
    const float* Wfk = (const float*)d_in[12];
    float* out = (float*)d_out;

    float *gq, *gk, *gkm, *gkp, *gkv, *gks;
    __half *gxh, *gvh, *gqf, *gkf, *goh, *gwh;
    cudaGetSymbolAddress((void**)&gq, g_q);
    cudaGetSymbolAddress((void**)&gk, g_k);
    cudaGetSymbolAddress((void**)&gkm, g_kmax);
    cudaGetSymbolAddress((void**)&gkp, g_kpart);
    cudaGetSymbolAddress((void**)&gkv, g_kv);
    cudaGetSymbolAddress((void**)&gks, g_ks);
    cudaGetSymbolAddress((void**)&gxh, g_xh);
    cudaGetSymbolAddress((void**)&gvh, g_vh);
    cudaGetSymbolAddress((void**)&gqf, g_qf);
    cudaGetSymbolAddress((void**)&gkf, g_kf);
    cudaGetSymbolAddress((void**)&goh, g_oh);
    cudaGetSymbolAddress((void**)&gwh, g_wh);

    const size_t WSZ = (size_t)DMODEL * DMODEL;  // 1M
    const size_t XSZ = (size_t)MROWS * DMODEL;   // 8M

    // weight transpose + fp16 round — 2 launches (keeps gemm at capture idx 3)
    WtBatch w0;
    w0.W[0] = Wq; w0.T[0] = gwh;
    w0.W[1] = Wk; w0.T[1] = gwh + WSZ;
    wt_cvt_kernel<<<dim3(32, 32, 2), 256>>>(w0);
    WtBatch w1;
    w1.W[0] = Wv; w1.T[0] = gwh + 2 * WSZ;
    w1.W[1] = Wo; w1.T[1] = gwh + 3 * WSZ;
    wt_cvt_kernel<<<dim3(32, 32, 2), 256>>>(w1);

    // input fp32 -> fp16 (batched)
    CvtBatch cb;
    cb.x[0] = queries; cb.x[1] = keys; cb.x[2] = values;
    for (int i = 0; i < 3; i++) cb.h[i] = gxh + i * XSZ;
    cvt_f16_kernel<<<dim3((int)(XSZ / 1024), 3), 256>>>(cb);

    // fp16 projections (batched): q,k -> fp32; v -> fp16 directly
    cudaFuncSetAttribute(gemm_f16, cudaFuncAttributeMaxDynamicSharedMemorySize, GM_SMEM);
    GemmBatch gb;
    for (int i = 0; i < 3; i++) {
        gb.A[i] = gxh + i * XSZ;
        gb.B[i] = gwh + i * WSZ;
    }
    gb.bias[0] = bq; gb.bias[1] = bk; gb.bias[2] = bv;
    gb.C[0] = gq; gb.C[1] = gk; gb.C[2] = gvh;
    gb.hout[0] = 0; gb.hout[1] = 0; gb.hout[2] = 1;
    gemm_f16<<<dim3(DMODEL / 128, MROWS / 128, 3), 256, GM_SMEM>>>(gb);

    // key global max
    kmax_part_kernel<<<dim3(16, NBH), 256>>>(gk, gkp);
    kmax_final_kernel<<<NBH, 16>>>(gkp, gkm);

    // FAVOR feature maps -> fp16 phi
    favor_kernel<<<dim3(NROWS / 64, 2), 256>>>(gq, gk, gqf, gkf, Wfq, Wfk, gkm);

    // chunked causal linear attention (HMMA)
    chunk_sum_kernel<<<dim3(NC, NBH), 256>>>(gkf, gvh, gkv, gks);
    prefix_kernel<<<dim3(4, NBH), 256>>>(gkv, gks);

    cudaFuncSetAttribute(chunk_attn_kernel,
                         cudaFuncAttributeMaxDynamicSharedMemorySize, CA_SMEM);
    chunk_attn_kernel<<<dim3(NC, NBH), 256, CA_SMEM>>>(gqf, gkf, gvh, gkv, gks, goh);

    // output projection (A = fp16 attn output, C = fp32 final out)
    GemmBatch ob;
    ob.A[0] = goh; ob.B[0] = gwh + 3 * WSZ; ob.bias[0] = bo;
    ob.C[0] = out; ob.hout[0] = 0;
    for (int i = 1; i < 3; i++) {
        ob.A[i] = goh; ob.B[i] = ob.B[0]; ob.bias[i] = bo;
        ob.C[i] = out; ob.hout[i] = 0;
    }
    gemm_f16<<<dim3(DMODEL / 128, MROWS / 128, 1), 256, GM_SMEM>>>(ob);
}

// round 15
// speedup vs baseline: 1.0886x; 1.0886x over previous
#include <cuda_runtime.h>
#include <cuda_fp16.h>
#include <math.h>
#include <stdint.h>

#define BB   2
#define LL   4096
#define HH   16
#define MM   64
#define DMODEL 1024
#define NROWS (BB*LL*HH)
#define DN    0.3535533905932738f
#define DIAGC 0.0625f
#define INVSQRTM 0.125f

#define CT   64
#define NC   (LL/CT)
#define NBH  (BB*HH)
#define MROWS (BB*LL)

// ---------------------------------------------------------------------------
// scratch
// ---------------------------------------------------------------------------
__device__ float g_q[MROWS*DMODEL];
__device__ float g_k[MROWS*DMODEL];
__device__ unsigned g_kmax_u[NBH];
__device__ float g_kv[NBH*NC*MM*MM];
__device__ float g_ks[NBH*NC*MM];
__device__ __align__(16) __half g_xh[3*MROWS*DMODEL];
__device__ __align__(16) __half g_vh[MROWS*DMODEL];
__device__ __align__(16) __half g_qf[MROWS*DMODEL];
__device__ __align__(16) __half g_kf[MROWS*DMODEL];
__device__ __align__(16) __half g_oh[MROWS*DMODEL];
__device__ __align__(16) __half g_wh[4*DMODEL*DMODEL];
__device__ __align__(16) __half g_sph[NBH*NC*MM*MM];
__device__ __align__(16) __half g_spl[NBH*NC*MM*MM];

// ---------------------------------------------------------------------------
// helpers
// ---------------------------------------------------------------------------
__device__ __forceinline__ uint32_t smem_to_u32(const void* p) {
    uint32_t a;
    asm("{ .reg .u64 t; cvta.to.shared.u64 t, %1; cvt.u32.u64 %0, t; }"
        : "=r"(a) : "l"(p));
    return a;
}
#define SWZ64(b) ((b) ^ (((b) >> 3) & 0x30))
#define SWZ128(b) ((b) ^ (((b) >> 3) & 0x70))

__device__ __forceinline__ void cp16(uint32_t dst, const void* src) {
    asm volatile("cp.async.cg.shared.global [%0], [%1], 16;" :: "r"(dst), "l"(src));
}
__device__ __forceinline__ void cp_commit() {
    asm volatile("cp.async.commit_group;" ::: "memory");
}
template<int N> __device__ __forceinline__ void cp_wait() {
    asm volatile("cp.async.wait_group %0;" :: "n"(N) : "memory");
}
__device__ __forceinline__ void ldsm4(uint32_t (&r)[4], uint32_t addr) {
    asm volatile("ldmatrix.sync.aligned.m8n8.x4.shared.b16 {%0,%1,%2,%3}, [%4];"
        : "=r"(r[0]), "=r"(r[1]), "=r"(r[2]), "=r"(r[3]) : "r"(addr));
}
__device__ __forceinline__ void ldsm4t(uint32_t (&r)[4], uint32_t addr) {
    asm volatile("ldmatrix.sync.aligned.m8n8.x4.trans.shared.b16 {%0,%1,%2,%3}, [%4];"
        : "=r"(r[0]), "=r"(r[1]), "=r"(r[2]), "=r"(r[3]) : "r"(addr));
}
__device__ __forceinline__ void mma_f16(float (&d)[4], const uint32_t (&a)[4],
                                        const uint32_t* b) {
    asm volatile("mma.sync.aligned.m16n8k16.row.col.f32.f16.f16.f32 "
        "{%0,%1,%2,%3}, {%4,%5,%6,%7}, {%8,%9}, {%0,%1,%2,%3};"
        : "+f"(d[0]), "+f"(d[1]), "+f"(d[2]), "+f"(d[3])
        : "r"(a[0]), "r"(a[1]), "r"(a[2]), "r"(a[3]), "r"(b[0]), "r"(b[1]));
}
__device__ __forceinline__ float fast_exp(float x) {
    float y = fmaxf(x * 1.4426950408889634f, -120.f);
    float n = rintf(y);
    float t = (y - n) * 0.6931471805599453f;
    float p = 1.f + t * (1.f + t * (0.5f + t * (0.16666667f
              + t * (0.041666667f + t * 0.0083333333f))));
    return p * __int_as_float(((int)n + 127) << 23);
}
// float -> order-preserving unsigned key (for atomicMax)
__device__ __forceinline__ unsigned fkey(float f) {
    unsigned b = __float_as_uint(f);
    return b ^ (unsigned)(((int)b >> 31) | 0x80000000);
}
__device__ __forceinline__ float fkey_dec(unsigned u) {
    unsigned b = (u & 0x80000000u) ? (u ^ 0x80000000u) : ~u;
    return __uint_as_float(b);
}

// ---------------------------------------------------------------------------
// fp16 HMMA GEMM (batched over grid.z): C = A[8192,1024] @ B^T + bias
//   kflag: fuse per-(b,h) max of output into g_kmax_u.
// ---------------------------------------------------------------------------
#define GM_TILE  8192
#define GM_STAGE (2*GM_TILE)
#define GM_NSTG  3
#define GM_SMEM  (GM_NSTG*GM_STAGE)
#define GM_NKC   32

struct GemmBatch {
    const __half *A[3], *B[3];
    const float* bias[3];
    void* C[3];
    int hout[3];
    int kflag[3];
};

__device__ __forceinline__ void gm_cp_chunk(
    uint32_t stage, const __half* A, const __half* B,
    int bm, int bn, int kc, int r_lo, int cb)
{
    const size_t ko = (size_t)kc * 64 + cb;
#pragma unroll
    for (int j = 0; j < 2; j++) {
        const int row = r_lo + 64 * j;
        const uint32_t swz = SWZ64((uint32_t)(row * 64 + cb));
        cp16(stage + swz,           (const char*)A + (size_t)(bm + row) * 2048 + ko);
        cp16(stage + GM_TILE + swz, (const char*)B + (size_t)(bn + row) * 2048 + ko);
    }
    cp_commit();
}

__device__ __forceinline__ void gm_compute(uint32_t st, int wm, int wn, int lid,
                                           float acc[2][8][4])
{
    const int ar  = wm + (lid & 15);
    const int akb = (lid >> 4) * 16;
    const int br  = (lid & 7) + ((lid >> 4) << 3);
    const int bkb = ((lid >> 3) & 1) * 16;
#pragma unroll
    for (int k0 = 0; k0 < 2; k0++) {
        const int kb = k0 * 32;
        uint32_t ah[2][4];
        ldsm4(ah[0], st + SWZ64((uint32_t)(ar * 64 + kb + akb)));
        ldsm4(ah[1], st + SWZ64((uint32_t)((ar + 16) * 64 + kb + akb)));
        uint32_t bh[4][4];
#pragma unroll
        for (int g = 0; g < 4; g++)
            ldsm4(bh[g], st + GM_TILE +
                  SWZ64((uint32_t)((wn + g * 16 + br) * 64 + kb + bkb)));
#pragma unroll
        for (int mt = 0; mt < 2; mt++)
#pragma unroll
            for (int g = 0; g < 4; g++) {
                mma_f16(acc[mt][2 * g],     ah[mt], &bh[g][0]);
                mma_f16(acc[mt][2 * g + 1], ah[mt], &bh[g][2]);
            }
    }
}

__global__ __launch_bounds__(256, 2)
void gemm_f16(GemmBatch batch, unsigned* km)
{
    extern __shared__ char smem[];
    __shared__ unsigned kms[2];
    const uint32_t sb = smem_to_u32(smem);
    const int tid = threadIdx.x;
    const int wid = tid >> 5, lid = tid & 31;
    const int gz = blockIdx.z;
    const __half* A = batch.A[gz];
    const __half* B = batch.B[gz];
    const float* bias = batch.bias[gz];

    const int bn = blockIdx.x * 128;
    const int bm = blockIdx.y * 128;
    const int r_lo = tid >> 2;
    const int cb = (tid & 3) * 16;
    const int wm = (wid & 3) * 32;
    const int wn = (wid >> 2) * 64;

    if (tid < 2) kms[tid] = 0;

    float acc[2][8][4];
#pragma unroll
    for (int mt = 0; mt < 2; mt++)
#pragma unroll
        for (int nt = 0; nt < 8; nt++)
#pragma unroll
            for (int j = 0; j < 4; j++) acc[mt][nt][j] = 0.f;

    gm_cp_chunk(sb + 0 * GM_STAGE, A, B, bm, bn, 0, r_lo, cb);
    gm_cp_chunk(sb + 1 * GM_STAGE, A, B, bm, bn, 1, r_lo, cb);

    uint32_t st_cur = sb;
    uint32_t st_nxt = sb + GM_STAGE;
    uint32_t st_fill = sb + 2 * GM_STAGE;
    for (int i = 0; i < GM_NKC; i++) {
        if (i == GM_NKC - 1) cp_wait<0>(); else cp_wait<1>();
        __syncthreads();
        if (i + 2 < GM_NKC)
            gm_cp_chunk(st_fill, A, B, bm, bn, i + 2, r_lo, cb);
        gm_compute(st_cur, wm, wn, lid, acc);
        uint32_t t = st_cur;
        st_cur = st_nxt; st_nxt = st_fill; st_fill = t;
    }

    const int row_b = bm + wm + (lid >> 2);
    const int col_b = bn + wn + (lid & 3) * 2;
    if (batch.hout[gz]) {
        __half* C = (__half*)batch.C[gz];
#pragma unroll
        for (int mt = 0; mt < 2; mt++) {
#pragma unroll
            for (int nt = 0; nt < 8; nt++) {
                const int col = col_b + nt * 8;
                const float b0 = bias[col], b1 = bias[col + 1];
                const int r0 = row_b + mt * 16;
                *(__half2*)&C[(size_t)r0 * DMODEL + col] =
                    __floats2half2_rn(acc[mt][nt][0] + b0, acc[mt][nt][1] + b1);
                *(__half2*)&C[(size_t)(r0 + 8) * DMODEL + col] =
                    __floats2half2_rn(acc[mt][nt][2] + b0, acc[mt][nt][3] + b1);
            }
        }
    } else {
        float* C = (float*)batch.C[gz];
#pragma unroll
        for (int mt = 0; mt < 2; mt++) {
#pragma unroll
            for (int nt = 0; nt < 8; nt++) {
                const int col = col_b + nt * 8;
                const float b0 = bias[col], b1 = bias[col + 1];
                const int r0 = row_b + mt * 16;
                float2 v0, v1;
                v0.x = acc[mt][nt][0] + b0; v0.y = acc[mt][nt][1] + b1;
                v1.x = acc[mt][nt][2] + b0; v1.y = acc[mt][nt][3] + b1;
                *(float2*)&C[(size_t)r0 * DMODEL + col] = v0;
                *(float2*)&C[(size_t)(r0 + 8) * DMODEL + col] = v1;
            }
        }
    }

    if (batch.kflag[gz]) {
        float lm = -1e30f;
#pragma unroll
        for (int mt = 0; mt < 2; mt++)
#pragma unroll
            for (int nt = 0; nt < 8; nt++) {
                const int col = col_b + nt * 8;
                const float b0 = bias[col], b1 = bias[col + 1];
                lm = fmaxf(lm, fmaxf(acc[mt][nt][0] + b0, acc[mt][nt][1] + b1));
                lm = fmaxf(lm, fmaxf(acc[mt][nt][2] + b0, acc[mt][nt][3] + b1));
            }
        atomicMax(&kms[wn >> 6], fkey(lm));
        __syncthreads();
        if (tid < 2)
            atomicMax(&km[(bm >> 12) * HH + (bn >> 6) + tid], kms[tid]);
    }
}

// ---------------------------------------------------------------------------
// fp32 -> fp16 conversion pass (batched over grid.y)
// ---------------------------------------------------------------------------
struct CvtBatch { const float* x[3]; __half* h[3]; };

__global__ __launch_bounds__(256)
void cvt_f16_kernel(CvtBatch batch)
{
    const float* x = batch.x[blockIdx.y];
    __half* h = batch.h[blockIdx.y];
    const int i = (blockIdx.x * 256 + threadIdx.x) * 4;
    float4 v = *(const float4*)(x + i);
    __half2* p = (__half2*)(h + i);
    p[0] = __floats2half2_rn(v.x, v.y);
    p[1] = __floats2half2_rn(v.z, v.w);
}

// ---------------------------------------------------------------------------
// weight transpose + fp16 round (batched over grid.z)
// ---------------------------------------------------------------------------
struct WtBatch { const float* W[2]; __half* T[2]; };

__global__ __launch_bounds__(256)
void wt_cvt_kernel(WtBatch batch)
{
    __shared__ float t[32][33];
    const float* W = batch.W[blockIdx.z];
    __half* T = batch.T[blockIdx.z];
    const int kx = blockIdx.x * 32;
    const int nx = blockIdx.y * 32;
    const int tx = threadIdx.x & 31, ty = threadIdx.x >> 5;
    for (int r = ty; r < 32; r += 8)
        t[r][tx] = W[(size_t)(kx + r) * DMODEL + nx + tx];
    __syncthreads();
    for (int r = ty; r < 32; r += 8)
        T[(size_t)(nx + r) * DMODEL + kx + tx] = __float2half_rn(t[tx][r]);
}

// ---------------------------------------------------------------------------
// FAVOR feature map: fp32 in -> fp16 phi out. grid.y: 0=query, 1=key.
// ---------------------------------------------------------------------------
#define FV_P 68
__global__ __launch_bounds__(256)
void favor_kernel(const float* __restrict__ Xq, const float* __restrict__ Xk,
                  __half* __restrict__ Oq, __half* __restrict__ Ok,
                  const float* __restrict__ Wfq, const float* __restrict__ Wfk,
                  const unsigned* __restrict__ kmaxu)
{
    __shared__ float Wt[64 * FV_P];
    __shared__ float xst[64 * FV_P];
    __shared__ float rowss[64];
    __shared__ float rowmx[64];

    const int is_query = (blockIdx.y == 0);
    const float* X = is_query ? Xq : Xk;
    __half* O = is_query ? Oq : Ok;
    const float* Wf = is_query ? Wfq : Wfk;
    const int tid = threadIdx.x;
    const int row0 = blockIdx.x * 64;

    for (int i = tid; i < 64 * 64; i += 256) {
        int d = i >> 6, m = i & 63;
        Wt[m * FV_P + d] = Wf[i];
    }
    {
        const int r = tid >> 2;
        const int m0 = (tid & 3) * 16;
        const float* src = X + (size_t)(row0 + r) * 64 + m0;
#pragma unroll
        for (int j4 = 0; j4 < 4; j4++) {
            float4 v = *(const float4*)(src + j4 * 4);
            int m = m0 + j4 * 4;
            xst[(m + 0) * FV_P + r] = DN * v.x;
            xst[(m + 1) * FV_P + r] = DN * v.y;
            xst[(m + 2) * FV_P + r] = DN * v.z;
            xst[(m + 3) * FV_P + r] = DN * v.w;
        }
    }
    __syncthreads();

    if (tid < 64) {
        float ss = 0.f, mx = -1e30f;
        for (int m = 0; m < 64; m++) {
            float x = xst[m * FV_P + tid];
            ss = fmaf(x, x, ss);
            mx = fmaxf(mx, x);
        }
        rowss[tid] = ss;
        rowmx[tid] = mx;
    }
    __syncthreads();

    const int tx = tid & 15, ty = tid >> 4;
    const int d0 = tx * 4, r0 = ty * 4;
    float acc[4][4];
#pragma unroll
    for (int i = 0; i < 4; i++)
#pragma unroll
        for (int j = 0; j < 4; j++) acc[i][j] = 0.f;

    for (int m = 0; m < 64; m++) {
        float4 w4 = *(float4*)&Wt[m * FV_P + d0];
        float4 x4 = *(float4*)&xst[m * FV_P + r0];
        float wf[4] = {w4.x, w4.y, w4.z, w4.w};
        float xf[4] = {x4.x, x4.y, x4.z, x4.w};
#pragma unroll
        for (int i = 0; i < 4; i++)
#pragma unroll
            for (int j = 0; j < 4; j++)
                acc[i][j] = fmaf(xf[i], wf[j], acc[i][j]);
    }

#pragma unroll
    for (int i = 0; i < 4; i++) {
        const int r = r0 + i;
        const int row = row0 + r;
        float mq;
        if (is_query) mq = rowmx[r];
        else mq = DN * fkey_dec(kmaxu[((row >> 16) << 4) + (row & 15)]);
        const float base = -DIAGC * rowss[r] - mq + 1e-8f;
        __half* dst = O + (size_t)row * 64 + d0;
        *(__half2*)dst = __floats2half2_rn(
            INVSQRTM * fast_exp(acc[i][0] + base),
            INVSQRTM * fast_exp(acc[i][1] + base));
        *(__half2*)(dst + 2) = __floats2half2_rn(
            INVSQRTM * fast_exp(acc[i][2] + base),
            INVSQRTM * fast_exp(acc[i][3] + base));
    }
}

// ---------------------------------------------------------------------------
// chunk_sum (HMMA, trans loads): KV[m][d] = sum_c K[c][m] V[c][d]
// Ks, Vs row-major [token][feat] SW128 (128B rows).
// ---------------------------------------------------------------------------
__global__ __launch_bounds__(256)
void chunk_sum_kernel(const __half* __restrict__ Kf, const __half* __restrict__ Vh,
                      float* __restrict__ kv, float* __restrict__ ks)
{
    __shared__ __align__(128) char sK[8192];
    __shared__ __align__(128) char sV[8192];
    const uint32_t kb = smem_to_u32(sK);
    const uint32_t vb = smem_to_u32(sV);

    const int c  = blockIdx.x;
    const int bh = blockIdx.y;
    const int b = bh >> 4, h = bh & 15;
    const int tid = threadIdx.x;
    const int wid = tid >> 5, lid = tid & 31;
    const size_t base = ((size_t)(b * LL + c * CT) * HH + h) * MM;
    const size_t stride = HH * MM;

    {   // row-major staging (vectorized)
        const int r = tid >> 2, q16 = (tid & 3) * 32;   // 32B quarter
        const uint32_t o0 = SWZ128((uint32_t)(r * 128 + q16));
        const uint32_t o1 = SWZ128((uint32_t)(r * 128 + q16 + 16));
        const char* ksrc = (const char*)(Kf + base + (size_t)r * stride) + q16;
        const char* vsrc = (const char*)(Vh + base + (size_t)r * stride) + q16;
        *(uint4*)(sK + o0) = *(const uint4*)ksrc;
        *(uint4*)(sK + o1) = *(const uint4*)(ksrc + 16);
        *(uint4*)(sV + o0) = *(const uint4*)vsrc;
        *(uint4*)(sV + o1) = *(const uint4*)(vsrc + 16);
    }
    __syncthreads();

    const int wm = (wid & 3) * 16;       // m tile
    const int wn = (wid >> 2) * 32;      // d tile
    // A = K^T (trans): lane -> K row, m-bytes
    const int a_rc = ((lid >> 4) & 1) * 8 + (lid & 7);
    const int a_mb = wm * 2 + ((lid >> 3) & 1) * 16;
    // B = V^T (trans): lane -> V row, d-bytes
    const int b_rc = ((lid >> 3) & 1) * 8 + (lid & 7);
    const int b_db = (lid >> 4) * 16;

    float acc[4][4];
#pragma unroll
    for (int nt = 0; nt < 4; nt++)
#pragma unroll
        for (int j = 0; j < 4; j++) acc[nt][j] = 0.f;

#pragma unroll
    for (int ksn = 0; ksn < 4; ksn++) {
        const int c0 = ksn * 16;
        uint32_t aa[4], b0[4], b1[4];
        ldsm4t(aa, kb + SWZ128((uint32_t)((c0 + a_rc) * 128 + a_mb)));
        ldsm4t(b0, vb + SWZ128((uint32_t)((c0 + b_rc) * 128 + wn * 2 + b_db)));
        ldsm4t(b1, vb + SWZ128((uint32_t)((c0 + b_rc) * 128 + (wn + 16) * 2 + b_db)));
        mma_f16(acc[0], aa, &b0[0]);
        mma_f16(acc[1], aa, &b0[2]);
        mma_f16(acc[2], aa, &b1[0]);
        mma_f16(acc[3], aa, &b1[2]);
    }

    float* out = kv + (size_t)(bh * NC + c) * MM * MM;
    const int fr = wm + (lid >> 2);
    const int fc = wn + (lid & 3) * 2;
#pragma unroll
    for (int nt = 0; nt < 4; nt++) {
        const int cc = fc + nt * 8;
        float2 lo, hi;
        lo.x = acc[nt][0]; lo.y = acc[nt][1];
        hi.x = acc[nt][2]; hi.y = acc[nt][3];
        *(float2*)&out[fr * 64 + cc] = lo;
        *(float2*)&out[(fr + 8) * 64 + cc] = hi;
    }

    if (tid < 64) {
        float s = 0.f;
        for (int cc = 0; cc < 64; cc++)
            s += __half2float(*(__half*)(sK + SWZ128((uint32_t)(cc * 128 + tid * 2))));
        ks[(size_t)(bh * NC + c) * MM + tid] = s;
    }
}

// ---------------------------------------------------------------------------
// prefix over chunks: kv(fp32) -> SpH/SpL fp16 pair (exclusive); ks in place.
// ---------------------------------------------------------------------------
__global__ __launch_bounds__(256)
void prefix_kernel(const float* __restrict__ kv, float* __restrict__ ks,
                   __half* __restrict__ spH, __half* __restrict__ spL)
{
    const int dg = blockIdx.x;
    const int bh = blockIdx.y;
    const int tid = threadIdx.x;
    const int m = tid >> 2;
    const int d = dg * 16 + (tid & 3) * 4;
    float4 run = make_float4(0.f, 0.f, 0.f, 0.f);
    for (int c = 0; c < NC; c++) {
        const size_t idx = ((size_t)(bh * NC + c) * MM + m) * MM + d;
        float4 val = *(const float4*)&kv[idx];
        __half h0 = __float2half_rn(run.x), h1 = __float2half_rn(run.y);
        __half h2 = __float2half_rn(run.z), h3 = __float2half_rn(run.w);
        __half2* ph = (__half2*)&spH[idx];
        ph[0] = __halves2half2(h0, h1); ph[1] = __halves2half2(h2, h3);
        __half2* pl = (__half2*)&spL[idx];
        pl[0] = __floats2half2_rn(run.x - __half2float(h0), run.y - __half2float(h1));
        pl[1] = __floats2half2_rn(run.z - __half2float(h2), run.w - __half2float(h3));
        run.x += val.x; run.y += val.y; run.z += val.z; run.w += val.w;
    }
    if (dg == 0 && tid < 64) {
        float r = 0.f;
        for (int c = 0; c < NC; c++) {
            float* p = ks + (size_t)(bh * NC + c) * MM + tid;
            float v = *p;
            *p = r;
            r += v;
        }
    }
}

// ---------------------------------------------------------------------------
// chunk_attn (full HMMA): QK^T -> mask -> As; o = As*V^T + Q*SpH^T + Q*SpL^T
// smem: Qs 0, Ks 8K, Vs 16K, As 24K, SpH 32K, SpL 40K, zpre 48K, den 48K+256
// ---------------------------------------------------------------------------
#define CA_SMEM (49152 + 512)
__global__ __launch_bounds__(256)
void chunk_attn_kernel(const __half* __restrict__ Qf, const __half* __restrict__ Kf,
                       const __half* __restrict__ Vh,
                       const __half* __restrict__ spH, const __half* __restrict__ spL,
                       const float* __restrict__ ksum, __half* __restrict__ Out)
{
    extern __shared__ char smc[];
    const uint32_t sb = smem_to_u32(smc);
    float* zpre = (float*)(smc + 49152);
    float* den  = (float*)(smc + 49152 + 256);

    const int c  = blockIdx.x;
    const int bh = blockIdx.y;
    const int b = bh >> 4, h = bh & 15;
    const int tid = threadIdx.x;
    const int wid = tid >> 5, lid = tid & 31;
    const size_t base = ((size_t)(b * LL + c * CT) * HH + h) * MM;
    const size_t stride = HH * MM;
    const size_t spbase = (size_t)(bh * NC + c) * MM * MM;

    {   // staging: Qs, Ks, Vs (strided rows), SpH, SpL (contiguous)
        const int r = tid >> 2, q16 = (tid & 3) * 32;
        const uint32_t o0 = SWZ128((uint32_t)(r * 128 + q16));
        const uint32_t o1 = SWZ128((uint32_t)(r * 128 + q16 + 16));
        const char* qsrc = (const char*)(Qf + base + (size_t)r * stride) + q16;
        const char* ksrc = (const char*)(Kf + base + (size_t)r * stride) + q16;
        const char* vsrc = (const char*)(Vh + base + (size_t)r * stride) + q16;
        const char* hsrc = (const char*)(spH + spbase + (size_t)r * 64) + q16;
        const char* lsrc = (const char*)(spL + spbase + (size_t)r * 64) + q16;
        *(uint4*)(smc + o0) = *(const uint4*)qsrc;
        *(uint4*)(smc + o1) = *(const uint4*)(qsrc + 16);
        *(uint4*)(smc + 8192 + o0) = *(const uint4*)ksrc;
        *(uint4*)(smc + 8192 + o1) = *(const uint4*)(ksrc + 16);
        *(uint4*)(smc + 16384 + o0) = *(const uint4*)vsrc;
        *(uint4*)(smc + 16384 + o1) = *(const uint4*)(vsrc + 16);
        *(uint4*)(smc + 32768 + o0) = *(const uint4*)hsrc;
        *(uint4*)(smc + 32768 + o1) = *(const uint4*)(hsrc + 16);
        *(uint4*)(smc + 40960 + o0) = *(const uint4*)lsrc;
        *(uint4*)(smc + 40960 + o1) = *(const uint4*)(lsrc + 16);
    }
    if (tid < 64) {
        zpre[tid] = ksum[(size_t)(bh * NC + c) * MM + tid];
        den[tid] = 0.f;
    }
    __syncthreads();

    const int wm = (wid & 3) * 16;
    const int wn = (wid >> 2) * 32;
    // plain A pattern (k along bytes): rows wm+(lid&15), kb + (lid>>4)*16
    const int a_ro = lid & 15;
    const int a_kb = (lid >> 4) * 16;
    // plain B pattern: rows wn + (lid&7) + ((lid>>4)<<3), kb + ((lid>>3)&1)*16
    const int b_ro = (lid & 7) + ((lid >> 4) << 3);
    const int b_kb = ((lid >> 3) & 1) * 16;
    // trans B pattern: rows c0 + ((lid>>3)&1)*8 + (lid&7), col-bytes + (lid>>4)*16
    const int t_rc = ((lid >> 3) & 1) * 8 + (lid & 7);
    const int t_db = (lid >> 4) * 16;

    // --- QK^T ---
    float a[4][4];
#pragma unroll
    for (int nt = 0; nt < 4; nt++)
#pragma unroll
        for (int j = 0; j < 4; j++) a[nt][j] = 0.f;
#pragma unroll
    for (int ksn = 0; ksn < 4; ksn++) {
        const int kb = ksn * 32;
        uint32_t aa[4], b0[4], b1[4];
        ldsm4(aa, sb + SWZ128((uint32_t)((wm + a_ro) * 128 + kb + a_kb)));
        ldsm4(b0, sb + 8192 + SWZ128((uint32_t)((wn + b_ro) * 128 + kb + b_kb)));
        ldsm4(b1, sb + 8192 + SWZ128((uint32_t)((wn + 16 + b_ro) * 128 + kb + b_kb)));
        mma_f16(a[0], aa, &b0[0]);
        mma_f16(a[1], aa, &b0[2]);
        mma_f16(a[2], aa, &b1[0]);
        mma_f16(a[3], aa, &b1[2]);
    }
    const int fr = wm + (lid >> 2);
    const int fcb = wn + (lid & 3) * 2;
    {
        float rs_lo = 0.f, rs_hi = 0.f;
#pragma unroll
        for (int nt = 0; nt < 4; nt++) {
            const int c0 = fcb + nt * 8;
            float v00 = (c0     <= fr)     ? a[nt][0] : 0.f;
            float v01 = (c0 + 1 <= fr)     ? a[nt][1] : 0.f;
            float v10 = (c0     <= fr + 8) ? a[nt][2] : 0.f;
            float v11 = (c0 + 1 <= fr + 8) ? a[nt][3] : 0.f;
            rs_lo += v00 + v01;
            rs_hi += v10 + v11;
            *(__half2*)(smc + 24576 + SWZ128((uint32_t)(fr * 128 + c0 * 2))) =
                __floats2half2_rn(v00, v01);
            *(__half2*)(smc + 24576 + SWZ128((uint32_t)((fr + 8) * 128 + c0 * 2))) =
                __floats2half2_rn(v10, v11);
        }
        atomicAdd(&den[fr], rs_lo);
        atomicAdd(&den[fr + 8], rs_hi);
    }
    __syncthreads();

    // --- o = As*V^T + Qs*SpH^T + Qs*SpL^T ---
    float o[4][4];
#pragma unroll
    for (int nt = 0; nt < 4; nt++)
#pragma unroll
        for (int j = 0; j < 4; j++) o[nt][j] = 0.f;
#pragma unroll
    for (int ksn = 0; ksn < 4; ksn++) {
        const int kb = ksn * 32;     // k-bytes for plain A loads
        const int k0 = ksn * 16;     // k-rows for trans B loads
        uint32_t aA[4], aQ[4], bv0[4], bv1[4], bh0[4], bh1[4], bl0[4], bl1[4];
        ldsm4(aA, sb + 24576 + SWZ128((uint32_t)((wm + a_ro) * 128 + kb + a_kb)));
        ldsm4(aQ, sb + SWZ128((uint32_t)((wm + a_ro) * 128 + kb + a_kb)));
        ldsm4t(bv0, sb + 16384 + SWZ128((uint32_t)((k0 + t_rc) * 128 + wn * 2 + t_db)));
        ldsm4t(bv1, sb + 16384 + SWZ128((uint32_t)((k0 + t_rc) * 128 + (wn + 16) * 2 + t_db)));
        ldsm4t(bh0, sb + 32768 + SWZ128((uint32_t)((k0 + t_rc) * 128 + wn * 2 + t_db)));
        ldsm4t(bh1, sb + 32768 + SWZ128((uint32_t)((k0 + t_rc) * 128 + (wn + 16) * 2 + t_db)));
        ldsm4t(bl0, sb + 40960 + SWZ128((uint32_t)((k0 + t_rc) * 128 + wn * 2 + t_db)));
        ldsm4t(bl1, sb + 40960 + SWZ128((uint32_t)((k0 + t_rc) * 128 + (wn + 16) * 2 + t_db)));
        mma_f16(o[0], aA, &bv0[0]); mma_f16(o[1], aA, &bv0[2]);
        mma_f16(o[2], aA, &bv1[0]); mma_f16(o[3], aA, &bv1[2]);
        mma_f16(o[0], aQ, &bh0[0]); mma_f16(o[1], aQ, &bh0[2]);
        mma_f16(o[2], aQ, &bh1[0]); mma_f16(o[3], aQ, &bh1[2]);
        mma_f16(o[0], aQ, &bl0[0]); mma_f16(o[1], aQ, &bl0[2]);
        mma_f16(o[2], aQ, &bl1[0]); mma_f16(o[3], aQ, &bl1[2]);
    }

    // den += Q . zpre (small scalar; swizzled reads: 8-way max conflict)
    if (tid < 64) {
        float s = den[tid];
        for (int m = 0; m < 64; m++)
            s = fmaf(__half2float(*(__half*)(smc + SWZ128((uint32_t)(tid * 128 + m * 2)))),
                     zpre[m], s);
        den[tid] = s;
    }
    __syncthreads();

    // --- write out from fragments ---
    const float d0inv = 1.f / den[fr];
    const float d1inv = 1.f / den[fr + 8];
#pragma unroll
    for (int nt = 0; nt < 4; nt++) {
        const int c0 = fcb + nt * 8;
        *(__half2*)&Out[base + (size_t)fr * stride + c0] =
            __floats2half2_rn(o[nt][0] * d0inv, o[nt][1] * d0inv);
        *(__half2*)&Out[base + (size_t)(fr + 8) * stride + c0] =
            __floats2half2_rn(o[nt][2] * d1inv, o[nt][3] * d1inv);
    }
}

// ---------------------------------------------------------------------------
// Launch
// ---------------------------------------------------------------------------
extern "C" void kernel_launch(void* const* d_in, const int* in_sizes, int n_in,
                              void* d_out, int out_size)
{
    const float* queries = (const float*)d_in[0];
    const float* keys    = (const float*)d_in[1];
    const float* values  = (const float*)d_in[2];
    const float* Wq = (const float*)d_in[3];
    const float* bq = (const float*)d_in[4];
    const float* Wk = (const float*)d_in[5];
    const float* bk = (const float*)d_in[6];
    const float* Wv = (const float*)d_in[7];
    const float* bv = (const float*)d_in[8];
    const float* Wo = (const float*)d_in[9];
    const float* bo = (const float*)d_in[10];
    const float* Wfq = (const float*)d_in[11];
    const float* Wfk = (const float*)d_in[12];
    float* out = (float*)d_out;

    float *gq, *gk, *gkv, *gks;
    unsigned* gkm;
    __half *gxh, *gvh, *gqf, *gkf, *goh, *gwh, *gsph, *gspl;
    cudaGetSymbolAddress((void**)&gq, g_q);
    cudaGetSymbolAddress((void**)&gk, g_k);
    cudaGetSymbolAddress((void**)&gkm, g_kmax_u);
    cudaGetSymbolAddress((void**)&gkv, g_kv);
    cudaGetSymbolAddress((void**)&gks, g_ks);
    cudaGetSymbolAddress((void**)&gxh, g_xh);
    cudaGetSymbolAddress((void**)&gvh, g_vh);
    cudaGetSymbolAddress((void**)&gqf, g_qf);
    cudaGetSymbolAddress((void**)&gkf, g_kf);
    cudaGetSymbolAddress((void**)&goh, g_oh);
    cudaGetSymbolAddress((void**)&gwh, g_wh);
    cudaGetSymbolAddress((void**)&gsph, g_sph);
    cudaGetSymbolAddress((void**)&gspl, g_spl);

    const size_t WSZ = (size_t)DMODEL * DMODEL;
    const size_t XSZ = (size_t)MROWS * DMODEL;

    cudaMemsetAsync(gkm, 0, NBH * sizeof(unsigned));

    WtBatch w0;
    w0.W[0] = Wq; w0.T[0] = gwh;
    w0.W[1] = Wk; w0.T[1] = gwh + WSZ;
    wt_cvt_kernel<<<dim3(32, 32, 2), 256>>>(w0);
    WtBatch w1;
    w1.W[0] = Wv; w1.T[0] = gwh + 2 * WSZ;
    w1.W[1] = Wo; w1.T[1] = gwh + 3 * WSZ;
    wt_cvt_kernel<<<dim3(32, 32, 2), 256>>>(w1);

    CvtBatch cb;
    cb.x[0] = queries; cb.x[1] = keys; cb.x[2] = values;
    for (int i = 0; i < 3; i++) cb.h[i] = gxh + i * XSZ;
    cvt_f16_kernel<<<dim3((int)(XSZ / 1024), 3), 256>>>(cb);

    cudaFuncSetAttribute(gemm_f16, cudaFuncAttributeMaxDynamicSharedMemorySize, GM_SMEM);
    GemmBatch gb;
    for (int i = 0; i < 3; i++) {
        gb.A[i] = gxh + i * XSZ;
        gb.B[i] = gwh + i * WSZ;
    }
    gb.bias[0] = bq; gb.bias[1] = bk; gb.bias[2] = bv;
    gb.C[0] = gq; gb.C[1] = gk; gb.C[2] = gvh;
    gb.hout[0] = 0; gb.hout[1] = 0; gb.hout[2] = 1;
    gb.kflag[0] = 0; gb.kflag[1] = 1; gb.kflag[2] = 0;
    gemm_f16<<<dim3(DMODEL / 128, MROWS / 128, 3), 256, GM_SMEM>>>(gb, gkm);

    favor_kernel<<<dim3(NROWS / 64, 2), 256>>>(gq, gk, gqf, gkf, Wfq, Wfk, gkm);

    chunk_sum_kernel<<<dim3(NC, NBH), 256>>>(gkf, gvh, gkv, gks);
    prefix_kernel<<<dim3(4, NBH), 256>>>(gkv, gks, gsph, gspl);

    cudaFuncSetAttribute(chunk_attn_kernel,
                         cudaFuncAttributeMaxDynamicSharedMemorySize, CA_SMEM);
    chunk_attn_kernel<<<dim3(NC, NBH), 256, CA_SMEM>>>(gqf, gkf, gvh, gsph, gspl, gks, goh);

    GemmBatch ob;
    ob.A[0] = goh; ob.B[0] = gwh + 3 * WSZ; ob.bias[0] = bo;
    ob.C[0] = out; ob.hout[0] = 0; ob.kflag[0] = 0;
    for (int i = 1; i < 3; i++) {
        ob.A[i] = goh; ob.B[i] = ob.B[0]; ob.bias[i] = bo;
        ob.C[i] = out; ob.hout[i] = 0; ob.kflag[i] = 0;
    }
    gemm_f16<<<dim3(DMODEL / 128, MROWS / 128, 1), 256, GM_SMEM>>>(ob, gkm);
}

// round 16
// speedup vs baseline: 1.2927x; 1.1875x over previous
#include <cuda_runtime.h>
#include <cuda_fp16.h>
#include <math.h>
#include <stdint.h>

#define BB   2
#define LL   4096
#define HH   16
#define MM   64
#define DMODEL 1024
#define NROWS (BB*LL*HH)
#define DN    0.3535533905932738f
#define DIAGC 0.0625f
#define INVSQRTM 0.125f

#define CT   64
#define NC   (LL/CT)
#define NBH  (BB*HH)
#define MROWS (BB*LL)

// ---------------------------------------------------------------------------
// scratch
// ---------------------------------------------------------------------------
__device__ float g_q[MROWS*DMODEL];
__device__ float g_k[MROWS*DMODEL];
__device__ float g_kmax[NBH];
__device__ float g_kpart[NBH*16];
__device__ float g_kv[NBH*NC*MM*MM];
__device__ float g_ks[NBH*NC*MM];
__device__ __align__(16) __half g_xh[3*MROWS*DMODEL];
__device__ __align__(16) __half g_vh[MROWS*DMODEL];
__device__ __align__(16) __half g_qf[MROWS*DMODEL];
__device__ __align__(16) __half g_kf[MROWS*DMODEL];
__device__ __align__(16) __half g_oh[MROWS*DMODEL];
__device__ __align__(16) __half g_wh[4*DMODEL*DMODEL];
__device__ __align__(16) __half g_sph[NBH*NC*MM*MM];
__device__ __align__(16) __half g_spl[NBH*NC*MM*MM];

// ---------------------------------------------------------------------------
// helpers
// ---------------------------------------------------------------------------
__device__ __forceinline__ uint32_t smem_to_u32(const void* p) {
    uint32_t a;
    asm("{ .reg .u64 t; cvta.to.shared.u64 t, %1; cvt.u32.u64 %0, t; }"
        : "=r"(a) : "l"(p));
    return a;
}
#define SWZ64(b) ((b) ^ (((b) >> 3) & 0x30))
#define SWZ128(b) ((b) ^ (((b) >> 3) & 0x70))

__device__ __forceinline__ void cp16(uint32_t dst, const void* src) {
    asm volatile("cp.async.cg.shared.global [%0], [%1], 16;" :: "r"(dst), "l"(src));
}
__device__ __forceinline__ void cp_commit() {
    asm volatile("cp.async.commit_group;" ::: "memory");
}
template<int N> __device__ __forceinline__ void cp_wait() {
    asm volatile("cp.async.wait_group %0;" :: "n"(N) : "memory");
}
__device__ __forceinline__ void ldsm4(uint32_t (&r)[4], uint32_t addr) {
    asm volatile("ldmatrix.sync.aligned.m8n8.x4.shared.b16 {%0,%1,%2,%3}, [%4];"
        : "=r"(r[0]), "=r"(r[1]), "=r"(r[2]), "=r"(r[3]) : "r"(addr));
}
__device__ __forceinline__ void ldsm4t(uint32_t (&r)[4], uint32_t addr) {
    asm volatile("ldmatrix.sync.aligned.m8n8.x4.trans.shared.b16 {%0,%1,%2,%3}, [%4];"
        : "=r"(r[0]), "=r"(r[1]), "=r"(r[2]), "=r"(r[3]) : "r"(addr));
}
__device__ __forceinline__ void mma_f16(float (&d)[4], const uint32_t (&a)[4],
                                        const uint32_t* b) {
    asm volatile("mma.sync.aligned.m16n8k16.row.col.f32.f16.f16.f32 "
        "{%0,%1,%2,%3}, {%4,%5,%6,%7}, {%8,%9}, {%0,%1,%2,%3};"
        : "+f"(d[0]), "+f"(d[1]), "+f"(d[2]), "+f"(d[3])
        : "r"(a[0]), "r"(a[1]), "r"(a[2]), "r"(a[3]), "r"(b[0]), "r"(b[1]));
}
__device__ __forceinline__ float fast_exp(float x) {
    float y = fmaxf(x * 1.4426950408889634f, -120.f);
    float n = rintf(y);
    float t = (y - n) * 0.6931471805599453f;
    float p = 1.f + t * (1.f + t * (0.5f + t * (0.16666667f
              + t * (0.041666667f + t * 0.0083333333f))));
    return p * __int_as_float(((int)n + 127) << 23);
}

// ---------------------------------------------------------------------------
// fp16 HMMA GEMM (batched over grid.z): C = A[8192,1024] @ B^T + bias
// (R13 version — no kmax fusion)
// ---------------------------------------------------------------------------
#define GM_TILE  8192
#define GM_STAGE (2*GM_TILE)
#define GM_NSTG  3
#define GM_SMEM  (GM_NSTG*GM_STAGE)
#define GM_NKC   32

struct GemmBatch {
    const __half *A[3], *B[3];
    const float* bias[3];
    void* C[3];
    int hout[3];
};

__device__ __forceinline__ void gm_cp_chunk(
    uint32_t stage, const __half* A, const __half* B,
    int bm, int bn, int kc, int r_lo, int cb)
{
    const size_t ko = (size_t)kc * 64 + cb;
#pragma unroll
    for (int j = 0; j < 2; j++) {
        const int row = r_lo + 64 * j;
        const uint32_t swz = SWZ64((uint32_t)(row * 64 + cb));
        cp16(stage + swz,           (const char*)A + (size_t)(bm + row) * 2048 + ko);
        cp16(stage + GM_TILE + swz, (const char*)B + (size_t)(bn + row) * 2048 + ko);
    }
    cp_commit();
}

__device__ __forceinline__ void gm_compute(uint32_t st, int wm, int wn, int lid,
                                           float acc[2][8][4])
{
    const int ar  = wm + (lid & 15);
    const int akb = (lid >> 4) * 16;
    const int br  = (lid & 7) + ((lid >> 4) << 3);
    const int bkb = ((lid >> 3) & 1) * 16;
#pragma unroll
    for (int k0 = 0; k0 < 2; k0++) {
        const int kb = k0 * 32;
        uint32_t ah[2][4];
        ldsm4(ah[0], st + SWZ64((uint32_t)(ar * 64 + kb + akb)));
        ldsm4(ah[1], st + SWZ64((uint32_t)((ar + 16) * 64 + kb + akb)));
        uint32_t bh[4][4];
#pragma unroll
        for (int g = 0; g < 4; g++)
            ldsm4(bh[g], st + GM_TILE +
                  SWZ64((uint32_t)((wn + g * 16 + br) * 64 + kb + bkb)));
#pragma unroll
        for (int mt = 0; mt < 2; mt++)
#pragma unroll
            for (int g = 0; g < 4; g++) {
                mma_f16(acc[mt][2 * g],     ah[mt], &bh[g][0]);
                mma_f16(acc[mt][2 * g + 1], ah[mt], &bh[g][2]);
            }
    }
}

__global__ __launch_bounds__(256, 2)
void gemm_f16(GemmBatch batch)
{
    extern __shared__ char smem[];
    const uint32_t sb = smem_to_u32(smem);
    const int tid = threadIdx.x;
    const int wid = tid >> 5, lid = tid & 31;
    const int gz = blockIdx.z;
    const __half* A = batch.A[gz];
    const __half* B = batch.B[gz];
    const float* bias = batch.bias[gz];

    const int bn = blockIdx.x * 128;
    const int bm = blockIdx.y * 128;
    const int r_lo = tid >> 2;
    const int cb = (tid & 3) * 16;
    const int wm = (wid & 3) * 32;
    const int wn = (wid >> 2) * 64;

    float acc[2][8][4];
#pragma unroll
    for (int mt = 0; mt < 2; mt++)
#pragma unroll
        for (int nt = 0; nt < 8; nt++)
#pragma unroll
            for (int j = 0; j < 4; j++) acc[mt][nt][j] = 0.f;

    gm_cp_chunk(sb + 0 * GM_STAGE, A, B, bm, bn, 0, r_lo, cb);
    gm_cp_chunk(sb + 1 * GM_STAGE, A, B, bm, bn, 1, r_lo, cb);

    uint32_t st_cur = sb;
    uint32_t st_nxt = sb + GM_STAGE;
    uint32_t st_fill = sb + 2 * GM_STAGE;
    for (int i = 0; i < GM_NKC; i++) {
        if (i == GM_NKC - 1) cp_wait<0>(); else cp_wait<1>();
        __syncthreads();
        if (i + 2 < GM_NKC)
            gm_cp_chunk(st_fill, A, B, bm, bn, i + 2, r_lo, cb);
        gm_compute(st_cur, wm, wn, lid, acc);
        uint32_t t = st_cur;
        st_cur = st_nxt; st_nxt = st_fill; st_fill = t;
    }

    const int row_b = bm + wm + (lid >> 2);
    const int col_b = bn + wn + (lid & 3) * 2;
    if (batch.hout[gz]) {
        __half* C = (__half*)batch.C[gz];
#pragma unroll
        for (int mt = 0; mt < 2; mt++) {
#pragma unroll
            for (int nt = 0; nt < 8; nt++) {
                const int col = col_b + nt * 8;
                const float b0 = bias[col], b1 = bias[col + 1];
                const int r0 = row_b + mt * 16;
                *(__half2*)&C[(size_t)r0 * DMODEL + col] =
                    __floats2half2_rn(acc[mt][nt][0] + b0, acc[mt][nt][1] + b1);
                *(__half2*)&C[(size_t)(r0 + 8) * DMODEL + col] =
                    __floats2half2_rn(acc[mt][nt][2] + b0, acc[mt][nt][3] + b1);
            }
        }
    } else {
        float* C = (float*)batch.C[gz];
#pragma unroll
        for (int mt = 0; mt < 2; mt++) {
#pragma unroll
            for (int nt = 0; nt < 8; nt++) {
                const int col = col_b + nt * 8;
                const float b0 = bias[col], b1 = bias[col + 1];
                const int r0 = row_b + mt * 16;
                float2 v0, v1;
                v0.x = acc[mt][nt][0] + b0; v0.y = acc[mt][nt][1] + b1;
                v1.x = acc[mt][nt][2] + b0; v1.y = acc[mt][nt][3] + b1;
                *(float2*)&C[(size_t)r0 * DMODEL + col] = v0;
                *(float2*)&C[(size_t)(r0 + 8) * DMODEL + col] = v1;
            }
        }
    }
}

// ---------------------------------------------------------------------------
// fp32 -> fp16 conversion pass (batched over grid.y)
// ---------------------------------------------------------------------------
struct CvtBatch { const float* x[3]; __half* h[3]; };

__global__ __launch_bounds__(256)
void cvt_f16_kernel(CvtBatch batch)
{
    const float* x = batch.x[blockIdx.y];
    __half* h = batch.h[blockIdx.y];
    const int i = (blockIdx.x * 256 + threadIdx.x) * 4;
    float4 v = *(const float4*)(x + i);
    __half2* p = (__half2*)(h + i);
    p[0] = __floats2half2_rn(v.x, v.y);
    p[1] = __floats2half2_rn(v.z, v.w);
}

// ---------------------------------------------------------------------------
// weight transpose + fp16 round (batched over grid.z)
// ---------------------------------------------------------------------------
struct WtBatch { const float* W[2]; __half* T[2]; };

__global__ __launch_bounds__(256)
void wt_cvt_kernel(WtBatch batch)
{
    __shared__ float t[32][33];
    const float* W = batch.W[blockIdx.z];
    __half* T = batch.T[blockIdx.z];
    const int kx = blockIdx.x * 32;
    const int nx = blockIdx.y * 32;
    const int tx = threadIdx.x & 31, ty = threadIdx.x >> 5;
    for (int r = ty; r < 32; r += 8)
        t[r][tx] = W[(size_t)(kx + r) * DMODEL + nx + tx];
    __syncthreads();
    for (int r = ty; r < 32; r += 8)
        T[(size_t)(nx + r) * DMODEL + kx + tx] = __float2half_rn(t[tx][r]);
}

// ---------------------------------------------------------------------------
// kmax (two stage)
// ---------------------------------------------------------------------------
__global__ void kmax_part_kernel(const float* __restrict__ Kp, float* __restrict__ kpart)
{
    const int bh = blockIdx.y, sl = blockIdx.x;
    const int b = bh >> 4, h = bh & 15;
    const int tid = threadIdx.x;
    float m = -1e30f;
    const int l0 = sl * 256;
    for (int idx = tid; idx < 256 * MM; idx += 256) {
        int l = l0 + (idx >> 6), mm = idx & 63;
        m = fmaxf(m, Kp[((size_t)(b * LL + l) * HH + h) * MM + mm]);
    }
    __shared__ float red[256];
    red[tid] = m;
    __syncthreads();
    for (int s = 128; s > 0; s >>= 1) {
        if (tid < s) red[tid] = fmaxf(red[tid], red[tid + s]);
        __syncthreads();
    }
    if (tid == 0) kpart[bh * 16 + sl] = red[0];
}

__global__ void kmax_final_kernel(const float* __restrict__ kpart, float* __restrict__ kmax)
{
    const int bh = blockIdx.x;
    const int t = threadIdx.x;
    __shared__ float red[16];
    red[t] = kpart[bh * 16 + t];
    __syncthreads();
    if (t < 8) red[t] = fmaxf(red[t], red[t + 8]);
    __syncthreads();
    if (t < 4) red[t] = fmaxf(red[t], red[t + 4]);
    __syncthreads();
    if (t == 0) kmax[bh] = DN * fmaxf(fmaxf(red[0], red[1]), fmaxf(red[2], red[3]));
}

// ---------------------------------------------------------------------------
// FAVOR feature map: fp32 in -> fp16 phi out. grid.y: 0=query, 1=key.
// ---------------------------------------------------------------------------
#define FV_P 68
__global__ __launch_bounds__(256)
void favor_kernel(const float* __restrict__ Xq, const float* __restrict__ Xk,
                  __half* __restrict__ Oq, __half* __restrict__ Ok,
                  const float* __restrict__ Wfq, const float* __restrict__ Wfk,
                  const float* __restrict__ kmax)
{
    __shared__ float Wt[64 * FV_P];
    __shared__ float xst[64 * FV_P];
    __shared__ float rowss[64];
    __shared__ float rowmx[64];

    const int is_query = (blockIdx.y == 0);
    const float* X = is_query ? Xq : Xk;
    __half* O = is_query ? Oq : Ok;
    const float* Wf = is_query ? Wfq : Wfk;
    const int tid = threadIdx.x;
    const int row0 = blockIdx.x * 64;

    for (int i = tid; i < 64 * 64; i += 256) {
        int d = i >> 6, m = i & 63;
        Wt[m * FV_P + d] = Wf[i];
    }
    {
        const int r = tid >> 2;
        const int m0 = (tid & 3) * 16;
        const float* src = X + (size_t)(row0 + r) * 64 + m0;
#pragma unroll
        for (int j4 = 0; j4 < 4; j4++) {
            float4 v = *(const float4*)(src + j4 * 4);
            int m = m0 + j4 * 4;
            xst[(m + 0) * FV_P + r] = DN * v.x;
            xst[(m + 1) * FV_P + r] = DN * v.y;
            xst[(m + 2) * FV_P + r] = DN * v.z;
            xst[(m + 3) * FV_P + r] = DN * v.w;
        }
    }
    __syncthreads();

    if (tid < 64) {
        float ss = 0.f, mx = -1e30f;
        for (int m = 0; m < 64; m++) {
            float x = xst[m * FV_P + tid];
            ss = fmaf(x, x, ss);
            mx = fmaxf(mx, x);
        }
        rowss[tid] = ss;
        rowmx[tid] = mx;
    }
    __syncthreads();

    const int tx = tid & 15, ty = tid >> 4;
    const int d0 = tx * 4, r0 = ty * 4;
    float acc[4][4];
#pragma unroll
    for (int i = 0; i < 4; i++)
#pragma unroll
        for (int j = 0; j < 4; j++) acc[i][j] = 0.f;

    for (int m = 0; m < 64; m++) {
        float4 w4 = *(float4*)&Wt[m * FV_P + d0];
        float4 x4 = *(float4*)&xst[m * FV_P + r0];
        float wf[4] = {w4.x, w4.y, w4.z, w4.w};
        float xf[4] = {x4.x, x4.y, x4.z, x4.w};
#pragma unroll
        for (int i = 0; i < 4; i++)
#pragma unroll
            for (int j = 0; j < 4; j++)
                acc[i][j] = fmaf(xf[i], wf[j], acc[i][j]);
    }

#pragma unroll
    for (int i = 0; i < 4; i++) {
        const int r = r0 + i;
        const int row = row0 + r;
        float mq;
        if (is_query) mq = rowmx[r];
        else          mq = kmax[((row >> 16) << 4) + (row & 15)];
        const float base = -DIAGC * rowss[r] - mq + 1e-8f;
        __half* dst = O + (size_t)row * 64 + d0;
        *(__half2*)dst = __floats2half2_rn(
            INVSQRTM * fast_exp(acc[i][0] + base),
            INVSQRTM * fast_exp(acc[i][1] + base));
        *(__half2*)(dst + 2) = __floats2half2_rn(
            INVSQRTM * fast_exp(acc[i][2] + base),
            INVSQRTM * fast_exp(acc[i][3] + base));
    }
}

// ---------------------------------------------------------------------------
// chunk_sum (HMMA, trans loads): KV[m][d] = sum_c K[c][m] V[c][d]
// ---------------------------------------------------------------------------
__global__ __launch_bounds__(256)
void chunk_sum_kernel(const __half* __restrict__ Kf, const __half* __restrict__ Vh,
                      float* __restrict__ kv, float* __restrict__ ks)
{
    __shared__ __align__(128) char sK[8192];
    __shared__ __align__(128) char sV[8192];
    const uint32_t kb = smem_to_u32(sK);
    const uint32_t vb = smem_to_u32(sV);

    const int c  = blockIdx.x;
    const int bh = blockIdx.y;
    const int b = bh >> 4, h = bh & 15;
    const int tid = threadIdx.x;
    const int wid = tid >> 5, lid = tid & 31;
    const size_t base = ((size_t)(b * LL + c * CT) * HH + h) * MM;
    const size_t stride = HH * MM;

    {
        const int r = tid >> 2, q16 = (tid & 3) * 32;
        const uint32_t o0 = SWZ128((uint32_t)(r * 128 + q16));
        const uint32_t o1 = SWZ128((uint32_t)(r * 128 + q16 + 16));
        const char* ksrc = (const char*)(Kf + base + (size_t)r * stride) + q16;
        const char* vsrc = (const char*)(Vh + base + (size_t)r * stride) + q16;
        *(uint4*)(sK + o0) = *(const uint4*)ksrc;
        *(uint4*)(sK + o1) = *(const uint4*)(ksrc + 16);
        *(uint4*)(sV + o0) = *(const uint4*)vsrc;
        *(uint4*)(sV + o1) = *(const uint4*)(vsrc + 16);
    }
    __syncthreads();

    const int wm = (wid & 3) * 16;
    const int wn = (wid >> 2) * 32;
    const int a_rc = ((lid >> 4) & 1) * 8 + (lid & 7);
    const int a_mb = wm * 2 + ((lid >> 3) & 1) * 16;
    const int b_rc = ((lid >> 3) & 1) * 8 + (lid & 7);
    const int b_db = (lid >> 4) * 16;

    float acc[4][4];
#pragma unroll
    for (int nt = 0; nt < 4; nt++)
#pragma unroll
        for (int j = 0; j < 4; j++) acc[nt][j] = 0.f;

#pragma unroll
    for (int ksn = 0; ksn < 4; ksn++) {
        const int c0 = ksn * 16;
        uint32_t aa[4], b0[4], b1[4];
        ldsm4t(aa, kb + SWZ128((uint32_t)((c0 + a_rc) * 128 + a_mb)));
        ldsm4t(b0, vb + SWZ128((uint32_t)((c0 + b_rc) * 128 + wn * 2 + b_db)));
        ldsm4t(b1, vb + SWZ128((uint32_t)((c0 + b_rc) * 128 + (wn + 16) * 2 + b_db)));
        mma_f16(acc[0], aa, &b0[0]);
        mma_f16(acc[1], aa, &b0[2]);
        mma_f16(acc[2], aa, &b1[0]);
        mma_f16(acc[3], aa, &b1[2]);
    }

    float* out = kv + (size_t)(bh * NC + c) * MM * MM;
    const int fr = wm + (lid >> 2);
    const int fc = wn + (lid & 3) * 2;
#pragma unroll
    for (int nt = 0; nt < 4; nt++) {
        const int cc = fc + nt * 8;
        float2 lo, hi;
        lo.x = acc[nt][0]; lo.y = acc[nt][1];
        hi.x = acc[nt][2]; hi.y = acc[nt][3];
        *(float2*)&out[fr * 64 + cc] = lo;
        *(float2*)&out[(fr + 8) * 64 + cc] = hi;
    }

    if (tid < 64) {
        float s = 0.f;
        for (int cc = 0; cc < 64; cc++)
            s += __half2float(*(__half*)(sK + SWZ128((uint32_t)(cc * 128 + tid * 2))));
        ks[(size_t)(bh * NC + c) * MM + tid] = s;
    }
}

// ---------------------------------------------------------------------------
// prefix over chunks: kv(fp32) -> SpH/SpL fp16 pair (exclusive); ks in place.
// ---------------------------------------------------------------------------
__global__ __launch_bounds__(256)
void prefix_kernel(const float* __restrict__ kv, float* __restrict__ ks,
                   __half* __restrict__ spH, __half* __restrict__ spL)
{
    const int dg = blockIdx.x;
    const int bh = blockIdx.y;
    const int tid = threadIdx.x;
    const int m = tid >> 2;
    const int d = dg * 16 + (tid & 3) * 4;
    float4 run = make_float4(0.f, 0.f, 0.f, 0.f);
    for (int c = 0; c < NC; c++) {
        const size_t idx = ((size_t)(bh * NC + c) * MM + m) * MM + d;
        float4 val = *(const float4*)&kv[idx];
        __half h0 = __float2half_rn(run.x), h1 = __float2half_rn(run.y);
        __half h2 = __float2half_rn(run.z), h3 = __float2half_rn(run.w);
        __half2* ph = (__half2*)&spH[idx];
        ph[0] = __halves2half2(h0, h1); ph[1] = __halves2half2(h2, h3);
        __half2* pl = (__half2*)&spL[idx];
        pl[0] = __floats2half2_rn(run.x - __half2float(h0), run.y - __half2float(h1));
        pl[1] = __floats2half2_rn(run.z - __half2float(h2), run.w - __half2float(h3));
        run.x += val.x; run.y += val.y; run.z += val.z; run.w += val.w;
    }
    if (dg == 0 && tid < 64) {
        float r = 0.f;
        for (int c = 0; c < NC; c++) {
            float* p = ks + (size_t)(bh * NC + c) * MM + tid;
            float v = *p;
            *p = r;
            r += v;
        }
    }
}

// ---------------------------------------------------------------------------
// chunk_attn (full HMMA): QK^T -> mask -> As; o = As*V^T + Q*SpH^T + Q*SpL^T
// ---------------------------------------------------------------------------
#define CA_SMEM (49152 + 512)
__global__ __launch_bounds__(256)
void chunk_attn_kernel(const __half* __restrict__ Qf, const __half* __restrict__ Kf,
                       const __half* __restrict__ Vh,
                       const __half* __restrict__ spH, const __half* __restrict__ spL,
                       const float* __restrict__ ksum, __half* __restrict__ Out)
{
    extern __shared__ char smc[];
    const uint32_t sb = smem_to_u32(smc);
    float* zpre = (float*)(smc + 49152);
    float* den  = (float*)(smc + 49152 + 256);

    const int c  = blockIdx.x;
    const int bh = blockIdx.y;
    const int b = bh >> 4, h = bh & 15;
    const int tid = threadIdx.x;
    const int wid = tid >> 5, lid = tid & 31;
    const size_t base = ((size_t)(b * LL + c * CT) * HH + h) * MM;
    const size_t stride = HH * MM;
    const size_t spbase = (size_t)(bh * NC + c) * MM * MM;

    {
        const int r = tid >> 2, q16 = (tid & 3) * 32;
        const uint32_t o0 = SWZ128((uint32_t)(r * 128 + q16));
        const uint32_t o1 = SWZ128((uint32_t)(r * 128 + q16 + 16));
        const char* qsrc = (const char*)(Qf + base + (size_t)r * stride) + q16;
        const char* ksrc = (const char*)(Kf + base + (size_t)r * stride) + q16;
        const char* vsrc = (const char*)(Vh + base + (size_t)r * stride) + q16;
        const char* hsrc = (const char*)(spH + spbase + (size_t)r * 64) + q16;
        const char* lsrc = (const char*)(spL + spbase + (size_t)r * 64) + q16;
        *(uint4*)(smc + o0) = *(const uint4*)qsrc;
        *(uint4*)(smc + o1) = *(const uint4*)(qsrc + 16);
        *(uint4*)(smc + 8192 + o0) = *(const uint4*)ksrc;
        *(uint4*)(smc + 8192 + o1) = *(const uint4*)(ksrc + 16);
        *(uint4*)(smc + 16384 + o0) = *(const uint4*)vsrc;
        *(uint4*)(smc + 16384 + o1) = *(const uint4*)(vsrc + 16);
        *(uint4*)(smc + 32768 + o0) = *(const uint4*)hsrc;
        *(uint4*)(smc + 32768 + o1) = *(const uint4*)(hsrc + 16);
        *(uint4*)(smc + 40960 + o0) = *(const uint4*)lsrc;
        *(uint4*)(smc + 40960 + o1) = *(const uint4*)(lsrc + 16);
    }
    if (tid < 64) {
        zpre[tid] = ksum[(size_t)(bh * NC + c) * MM + tid];
        den[tid] = 0.f;
    }
    __syncthreads();

    const int wm = (wid & 3) * 16;
    const int wn = (wid >> 2) * 32;
    const int a_ro = lid & 15;
    const int a_kb = (lid >> 4) * 16;
    const int b_ro = (lid & 7) + ((lid >> 4) << 3);
    const int b_kb = ((lid >> 3) & 1) * 16;
    const int t_rc = ((lid >> 3) & 1) * 8 + (lid & 7);
    const int t_db = (lid >> 4) * 16;

    float a[4][4];
#pragma unroll
    for (int nt = 0; nt < 4; nt++)
#pragma unroll
        for (int j = 0; j < 4; j++) a[nt][j] = 0.f;
#pragma unroll
    for (int ksn = 0; ksn < 4; ksn++) {
        const int kb = ksn * 32;
        uint32_t aa[4], b0[4], b1[4];
        ldsm4(aa, sb + SWZ128((uint32_t)((wm + a_ro) * 128 + kb + a_kb)));
        ldsm4(b0, sb + 8192 + SWZ128((uint32_t)((wn + b_ro) * 128 + kb + b_kb)));
        ldsm4(b1, sb + 8192 + SWZ128((uint32_t)((wn + 16 + b_ro) * 128 + kb + b_kb)));
        mma_f16(a[0], aa, &b0[0]);
        mma_f16(a[1], aa, &b0[2]);
        mma_f16(a[2], aa, &b1[0]);
        mma_f16(a[3], aa, &b1[2]);
    }
    const int fr = wm + (lid >> 2);
    const int fcb = wn + (lid & 3) * 2;
    {
        float rs_lo = 0.f, rs_hi = 0.f;
#pragma unroll
        for (int nt = 0; nt < 4; nt++) {
            const int c0 = fcb + nt * 8;
            float v00 = (c0     <= fr)     ? a[nt][0] : 0.f;
            float v01 = (c0 + 1 <= fr)     ? a[nt][1] : 0.f;
            float v10 = (c0     <= fr + 8) ? a[nt][2] : 0.f;
            float v11 = (c0 + 1 <= fr + 8) ? a[nt][3] : 0.f;
            rs_lo += v00 + v01;
            rs_hi += v10 + v11;
            *(__half2*)(smc + 24576 + SWZ128((uint32_t)(fr * 128 + c0 * 2))) =
                __floats2half2_rn(v00, v01);
            *(__half2*)(smc + 24576 + SWZ128((uint32_t)((fr + 8) * 128 + c0 * 2))) =
                __floats2half2_rn(v10, v11);
        }
        atomicAdd(&den[fr], rs_lo);
        atomicAdd(&den[fr + 8], rs_hi);
    }
    __syncthreads();

    float o[4][4];
#pragma unroll
    for (int nt = 0; nt < 4; nt++)
#pragma unroll
        for (int j = 0; j < 4; j++) o[nt][j] = 0.f;
#pragma unroll
    for (int ksn = 0; ksn < 4; ksn++) {
        const int kb = ksn * 32;
        const int k0 = ksn * 16;
        uint32_t aA[4], aQ[4], bv0[4], bv1[4], bh0[4], bh1[4], bl0[4], bl1[4];
        ldsm4(aA, sb + 24576 + SWZ128((uint32_t)((wm + a_ro) * 128 + kb + a_kb)));
        ldsm4(aQ, sb + SWZ128((uint32_t)((wm + a_ro) * 128 + kb + a_kb)));
        ldsm4t(bv0, sb + 16384 + SWZ128((uint32_t)((k0 + t_rc) * 128 + wn * 2 + t_db)));
        ldsm4t(bv1, sb + 16384 + SWZ128((uint32_t)((k0 + t_rc) * 128 + (wn + 16) * 2 + t_db)));
        ldsm4t(bh0, sb + 32768 + SWZ128((uint32_t)((k0 + t_rc) * 128 + wn * 2 + t_db)));
        ldsm4t(bh1, sb + 32768 + SWZ128((uint32_t)((k0 + t_rc) * 128 + (wn + 16) * 2 + t_db)));
        ldsm4t(bl0, sb + 40960 + SWZ128((uint32_t)((k0 + t_rc) * 128 + wn * 2 + t_db)));
        ldsm4t(bl1, sb + 40960 + SWZ128((uint32_t)((k0 + t_rc) * 128 + (wn + 16) * 2 + t_db)));
        mma_f16(o[0], aA, &bv0[0]); mma_f16(o[1], aA, &bv0[2]);
        mma_f16(o[2], aA, &bv1[0]); mma_f16(o[3], aA, &bv1[2]);
        mma_f16(o[0], aQ, &bh0[0]); mma_f16(o[1], aQ, &bh0[2]);
        mma_f16(o[2], aQ, &bh1[0]); mma_f16(o[3], aQ, &bh1[2]);
        mma_f16(o[0], aQ, &bl0[0]); mma_f16(o[1], aQ, &bl0[2]);
        mma_f16(o[2], aQ, &bl1[0]); mma_f16(o[3], aQ, &bl1[2]);
    }

    if (tid < 64) {
        float s = den[tid];
        for (int m = 0; m < 64; m++)
            s = fmaf(__half2float(*(__half*)(smc + SWZ128((uint32_t)(tid * 128 + m * 2)))),
                     zpre[m], s);
        den[tid] = s;
    }
    __syncthreads();

    const float d0inv = 1.f / den[fr];
    const float d1inv = 1.f / den[fr + 8];
#pragma unroll
    for (int nt = 0; nt < 4; nt++) {
        const int c0 = fcb + nt * 8;
        *(__half2*)&Out[base + (size_t)fr * stride + c0] =
            __floats2half2_rn(o[nt][0] * d0inv, o[nt][1] * d0inv);
        *(__half2*)&Out[base + (size_t)(fr + 8) * stride + c0] =
            __floats2half2_rn(o[nt][2] * d1inv, o[nt][3] * d1inv);
    }
}

// ---------------------------------------------------------------------------
// Launch
// ---------------------------------------------------------------------------
extern "C" void kernel_launch(void* const* d_in, const int* in_sizes, int n_in,
                              void* d_out, int out_size)
{
    const float* queries = (const float*)d_in[0];
    const float* keys    = (const float*)d_in[1];
    const float* values  = (const float*)d_in[2];
    const float* Wq = (const float*)d_in[3];
    const float* bq = (const float*)d_in[4];
    const float* Wk = (const float*)d_in[5];
    const float* bk = (const float*)d_in[6];
    const float* Wv = (const float*)d_in[7];
    const float* bv = (const float*)d_in[8];
    const float* Wo = (const float*)d_in[9];
    const float* bo = (const float*)d_in[10];
    const float* Wfq = (const float*)d_in[11];
    const float* Wfk = (const float*)d_in[12];
    float* out = (float*)d_out;

    float *gq, *gk, *gkm, *gkp, *gkv, *gks;
    __half *gxh, *gvh, *gqf, *gkf, *goh, *gwh, *gsph, *gspl;
    cudaGetSymbolAddress((void**)&gq, g_q);
    cudaGetSymbolAddress((void**)&gk, g_k);
    cudaGetSymbolAddress((void**)&gkm, g_kmax);
    cudaGetSymbolAddress((void**)&gkp, g_kpart);
    cudaGetSymbolAddress((void**)&gkv, g_kv);
    cudaGetSymbolAddress((void**)&gks, g_ks);
    cudaGetSymbolAddress((void**)&gxh, g_xh);
    cudaGetSymbolAddress((void**)&gvh, g_vh);
    cudaGetSymbolAddress((void**)&gqf, g_qf);
    cudaGetSymbolAddress((void**)&gkf, g_kf);
    cudaGetSymbolAddress((void**)&goh, g_oh);
    cudaGetSymbolAddress((void**)&gwh, g_wh);
    cudaGetSymbolAddress((void**)&gsph, g_sph);
    cudaGetSymbolAddress((void**)&gspl, g_spl);

    const size_t WSZ = (size_t)DMODEL * DMODEL;
    const size_t XSZ = (size_t)MROWS * DMODEL;

    WtBatch w0;
    w0.W[0] = Wq; w0.T[0] = gwh;
    w0.W[1] = Wk; w0.T[1] = gwh + WSZ;
    wt_cvt_kernel<<<dim3(32, 32, 2), 256>>>(w0);
    WtBatch w1;
    w1.W[0] = Wv; w1.T[0] = gwh + 2 * WSZ;
    w1.W[1] = Wo; w1.T[1] = gwh + 3 * WSZ;
    wt_cvt_kernel<<<dim3(32, 32, 2), 256>>>(w1);

    CvtBatch cb;
    cb.x[0] = queries; cb.x[1] = keys; cb.x[2] = values;
    for (int i = 0; i < 3; i++) cb.h[i] = gxh + i * XSZ;
    cvt_f16_kernel<<<dim3((int)(XSZ / 1024), 3), 256>>>(cb);

    cudaFuncSetAttribute(gemm_f16, cudaFuncAttributeMaxDynamicSharedMemorySize, GM_SMEM);
    GemmBatch gb;
    for (int i = 0; i < 3; i++) {
        gb.A[i] = gxh + i * XSZ;
        gb.B[i] = gwh + i * WSZ;
    }
    gb.bias[0] = bq; gb.bias[1] = bk; gb.bias[2] = bv;
    gb.C[0] = gq; gb.C[1] = gk; gb.C[2] = gvh;
    gb.hout[0] = 0; gb.hout[1] = 0; gb.hout[2] = 1;
    gemm_f16<<<dim3(DMODEL / 128, MROWS / 128, 3), 256, GM_SMEM>>>(gb);

    kmax_part_kernel<<<dim3(16, NBH), 256>>>(gk, gkp);
    kmax_final_kernel<<<NBH, 16>>>(gkp, gkm);

    favor_kernel<<<dim3(NROWS / 64, 2), 256>>>(gq, gk, gqf, gkf, Wfq, Wfk, gkm);

    chunk_sum_kernel<<<dim3(NC, NBH), 256>>>(gkf, gvh, gkv, gks);
    prefix_kernel<<<dim3(4, NBH), 256>>>(gkv, gks, gsph, gspl);

    cudaFuncSetAttribute(chunk_attn_kernel,
                         cudaFuncAttributeMaxDynamicSharedMemorySize, CA_SMEM);
    chunk_attn_kernel<<<dim3(NC, NBH), 256, CA_SMEM>>>(gqf, gkf, gvh, gsph, gspl, gks, goh);

    GemmBatch ob;
    ob.A[0] = goh; ob.B[0] = gwh + 3 * WSZ; ob.bias[0] = bo;
    ob.C[0] = out; ob.hout[0] = 0;
    for (int i = 1; i < 3; i++) {
        ob.A[i] = goh; ob.B[i] = ob.B[0]; ob.bias[i] = bo;
        ob.C[i] = out; ob.hout[i] = 0;
    }
    gemm_f16<<<dim3(DMODEL / 128, MROWS / 128, 1), 256, GM_SMEM>>>(ob);
}

// round 17
// speedup vs baseline: 1.3140x; 1.0165x over previous
#include <cuda_runtime.h>
#include <cuda_fp16.h>
#include <math.h>
#include <stdint.h>

#define BB   2
#define LL   4096
#define HH   16
#define MM   64
#define DMODEL 1024
#define NROWS (BB*LL*HH)
#define DN    0.3535533905932738f
#define DIAGC 0.0625f
#define INVSQRTM 0.125f

#define CT   64
#define NC   (LL/CT)
#define NBH  (BB*HH)
#define MROWS (BB*LL)

// ---------------------------------------------------------------------------
// scratch
// ---------------------------------------------------------------------------
__device__ float g_q[MROWS*DMODEL];
__device__ float g_k[MROWS*DMODEL];
__device__ unsigned g_kmax_u[NBH];
__device__ float g_kv[NBH*NC*MM*MM];
__device__ float g_ks[NBH*NC*MM];
__device__ __align__(16) __half g_xh[3*MROWS*DMODEL];
__device__ __align__(16) __half g_vh[MROWS*DMODEL];
__device__ __align__(16) __half g_qf[MROWS*DMODEL];
__device__ __align__(16) __half g_kf[MROWS*DMODEL];
__device__ __align__(16) __half g_oh[MROWS*DMODEL];
__device__ __align__(16) __half g_wh[4*DMODEL*DMODEL];
__device__ __align__(16) __half g_sph[NBH*NC*MM*MM];
__device__ __align__(16) __half g_spl[NBH*NC*MM*MM];

// ---------------------------------------------------------------------------
// helpers
// ---------------------------------------------------------------------------
__device__ __forceinline__ uint32_t smem_to_u32(const void* p) {
    uint32_t a;
    asm("{ .reg .u64 t; cvta.to.shared.u64 t, %1; cvt.u32.u64 %0, t; }"
        : "=r"(a) : "l"(p));
    return a;
}
#define SWZ64(b) ((b) ^ (((b) >> 3) & 0x30))
#define SWZ128(b) ((b) ^ (((b) >> 3) & 0x70))

__device__ __forceinline__ void cp16(uint32_t dst, const void* src) {
    asm volatile("cp.async.cg.shared.global [%0], [%1], 16;" :: "r"(dst), "l"(src));
}
__device__ __forceinline__ void cp_commit() {
    asm volatile("cp.async.commit_group;" ::: "memory");
}
template<int N> __device__ __forceinline__ void cp_wait() {
    asm volatile("cp.async.wait_group %0;" :: "n"(N) : "memory");
}
__device__ __forceinline__ void ldsm4(uint32_t (&r)[4], uint32_t addr) {
    asm volatile("ldmatrix.sync.aligned.m8n8.x4.shared.b16 {%0,%1,%2,%3}, [%4];"
        : "=r"(r[0]), "=r"(r[1]), "=r"(r[2]), "=r"(r[3]) : "r"(addr));
}
__device__ __forceinline__ void ldsm4t(uint32_t (&r)[4], uint32_t addr) {
    asm volatile("ldmatrix.sync.aligned.m8n8.x4.trans.shared.b16 {%0,%1,%2,%3}, [%4];"
        : "=r"(r[0]), "=r"(r[1]), "=r"(r[2]), "=r"(r[3]) : "r"(addr));
}
__device__ __forceinline__ void mma_f16(float (&d)[4], const uint32_t (&a)[4],
                                        const uint32_t* b) {
    asm volatile("mma.sync.aligned.m16n8k16.row.col.f32.f16.f16.f32 "
        "{%0,%1,%2,%3}, {%4,%5,%6,%7}, {%8,%9}, {%0,%1,%2,%3};"
        : "+f"(d[0]), "+f"(d[1]), "+f"(d[2]), "+f"(d[3])
        : "r"(a[0]), "r"(a[1]), "r"(a[2]), "r"(a[3]), "r"(b[0]), "r"(b[1]));
}
__device__ __forceinline__ float fast_exp(float x) {
    float y = fmaxf(x * 1.4426950408889634f, -120.f);
    float n = rintf(y);
    float t = (y - n) * 0.6931471805599453f;
    float p = 1.f + t * (1.f + t * (0.5f + t * (0.16666667f
              + t * (0.041666667f + t * 0.0083333333f))));
    return p * __int_as_float(((int)n + 127) << 23);
}
// order-preserving float <-> uint keys (memset-0 == -inf)
__device__ __forceinline__ unsigned fkey(float f) {
    unsigned b = __float_as_uint(f);
    return b ^ (unsigned)(((int)b >> 31) | 0x80000000);
}
__device__ __forceinline__ float fkey_dec(unsigned u) {
    unsigned b = (u & 0x80000000u) ? (u ^ 0x80000000u) : ~u;
    return __uint_as_float(b);
}

// ---------------------------------------------------------------------------
// fp16 HMMA GEMM (batched over grid.z): C = A[8192,1024] @ B^T + bias
// ---------------------------------------------------------------------------
#define GM_TILE  8192
#define GM_STAGE (2*GM_TILE)
#define GM_NSTG  3
#define GM_SMEM  (GM_NSTG*GM_STAGE)
#define GM_NKC   32

struct GemmBatch {
    const __half *A[3], *B[3];
    const float* bias[3];
    void* C[3];
    int hout[3];
};

__device__ __forceinline__ void gm_cp_chunk(
    uint32_t stage, const __half* A, const __half* B,
    int bm, int bn, int kc, int r_lo, int cb)
{
    const size_t ko = (size_t)kc * 64 + cb;
#pragma unroll
    for (int j = 0; j < 2; j++) {
        const int row = r_lo + 64 * j;
        const uint32_t swz = SWZ64((uint32_t)(row * 64 + cb));
        cp16(stage + swz,           (const char*)A + (size_t)(bm + row) * 2048 + ko);
        cp16(stage + GM_TILE + swz, (const char*)B + (size_t)(bn + row) * 2048 + ko);
    }
    cp_commit();
}

__device__ __forceinline__ void gm_compute(uint32_t st, int wm, int wn, int lid,
                                           float acc[2][8][4])
{
    const int ar  = wm + (lid & 15);
    const int akb = (lid >> 4) * 16;
    const int br  = (lid & 7) + ((lid >> 4) << 3);
    const int bkb = ((lid >> 3) & 1) * 16;
#pragma unroll
    for (int k0 = 0; k0 < 2; k0++) {
        const int kb = k0 * 32;
        uint32_t ah[2][4];
        ldsm4(ah[0], st + SWZ64((uint32_t)(ar * 64 + kb + akb)));
        ldsm4(ah[1], st + SWZ64((uint32_t)((ar + 16) * 64 + kb + akb)));
        uint32_t bh[4][4];
#pragma unroll
        for (int g = 0; g < 4; g++)
            ldsm4(bh[g], st + GM_TILE +
                  SWZ64((uint32_t)((wn + g * 16 + br) * 64 + kb + bkb)));
#pragma unroll
        for (int mt = 0; mt < 2; mt++)
#pragma unroll
            for (int g = 0; g < 4; g++) {
                mma_f16(acc[mt][2 * g],     ah[mt], &bh[g][0]);
                mma_f16(acc[mt][2 * g + 1], ah[mt], &bh[g][2]);
            }
    }
}

__global__ __launch_bounds__(256, 2)
void gemm_f16(GemmBatch batch)
{
    extern __shared__ char smem[];
    const uint32_t sb = smem_to_u32(smem);
    const int tid = threadIdx.x;
    const int wid = tid >> 5, lid = tid & 31;
    const int gz = blockIdx.z;
    const __half* A = batch.A[gz];
    const __half* B = batch.B[gz];
    const float* bias = batch.bias[gz];

    const int bn = blockIdx.x * 128;
    const int bm = blockIdx.y * 128;
    const int r_lo = tid >> 2;
    const int cb = (tid & 3) * 16;
    const int wm = (wid & 3) * 32;
    const int wn = (wid >> 2) * 64;

    float acc[2][8][4];
#pragma unroll
    for (int mt = 0; mt < 2; mt++)
#pragma unroll
        for (int nt = 0; nt < 8; nt++)
#pragma unroll
            for (int j = 0; j < 4; j++) acc[mt][nt][j] = 0.f;

    gm_cp_chunk(sb + 0 * GM_STAGE, A, B, bm, bn, 0, r_lo, cb);
    gm_cp_chunk(sb + 1 * GM_STAGE, A, B, bm, bn, 1, r_lo, cb);

    uint32_t st_cur = sb;
    uint32_t st_nxt = sb + GM_STAGE;
    uint32_t st_fill = sb + 2 * GM_STAGE;
    for (int i = 0; i < GM_NKC; i++) {
        if (i == GM_NKC - 1) cp_wait<0>(); else cp_wait<1>();
        __syncthreads();
        if (i + 2 < GM_NKC)
            gm_cp_chunk(st_fill, A, B, bm, bn, i + 2, r_lo, cb);
        gm_compute(st_cur, wm, wn, lid, acc);
        uint32_t t = st_cur;
        st_cur = st_nxt; st_nxt = st_fill; st_fill = t;
    }

    const int row_b = bm + wm + (lid >> 2);
    const int col_b = bn + wn + (lid & 3) * 2;
    if (batch.hout[gz]) {
        __half* C = (__half*)batch.C[gz];
#pragma unroll
        for (int mt = 0; mt < 2; mt++) {
#pragma unroll
            for (int nt = 0; nt < 8; nt++) {
                const int col = col_b + nt * 8;
                const float b0 = bias[col], b1 = bias[col + 1];
                const int r0 = row_b + mt * 16;
                *(__half2*)&C[(size_t)r0 * DMODEL + col] =
                    __floats2half2_rn(acc[mt][nt][0] + b0, acc[mt][nt][1] + b1);
                *(__half2*)&C[(size_t)(r0 + 8) * DMODEL + col] =
                    __floats2half2_rn(acc[mt][nt][2] + b0, acc[mt][nt][3] + b1);
            }
        }
    } else {
        float* C = (float*)batch.C[gz];
#pragma unroll
        for (int mt = 0; mt < 2; mt++) {
#pragma unroll
            for (int nt = 0; nt < 8; nt++) {
                const int col = col_b + nt * 8;
                const float b0 = bias[col], b1 = bias[col + 1];
                const int r0 = row_b + mt * 16;
                float2 v0, v1;
                v0.x = acc[mt][nt][0] + b0; v0.y = acc[mt][nt][1] + b1;
                v1.x = acc[mt][nt][2] + b0; v1.y = acc[mt][nt][3] + b1;
                *(float2*)&C[(size_t)r0 * DMODEL + col] = v0;
                *(float2*)&C[(size_t)(r0 + 8) * DMODEL + col] = v1;
            }
        }
    }
}

// ---------------------------------------------------------------------------
// fp32 -> fp16 conversion pass (batched over grid.y)
// ---------------------------------------------------------------------------
struct CvtBatch { const float* x[3]; __half* h[3]; };

__global__ __launch_bounds__(256)
void cvt_f16_kernel(CvtBatch batch)
{
    const float* x = batch.x[blockIdx.y];
    __half* h = batch.h[blockIdx.y];
    const int i = (blockIdx.x * 256 + threadIdx.x) * 4;
    float4 v = *(const float4*)(x + i);
    __half2* p = (__half2*)(h + i);
    p[0] = __floats2half2_rn(v.x, v.y);
    p[1] = __floats2half2_rn(v.z, v.w);
}

// ---------------------------------------------------------------------------
// weight transpose + fp16 round (grid.z = 4, single launch)
// ---------------------------------------------------------------------------
struct WtBatch { const float* W[4]; __half* T[4]; };

__global__ __launch_bounds__(256)
void wt_cvt_kernel(WtBatch batch)
{
    __shared__ float t[32][33];
    const float* W = batch.W[blockIdx.z];
    __half* T = batch.T[blockIdx.z];
    const int kx = blockIdx.x * 32;
    const int nx = blockIdx.y * 32;
    const int tx = threadIdx.x & 31, ty = threadIdx.x >> 5;
    for (int r = ty; r < 32; r += 8)
        t[r][tx] = W[(size_t)(kx + r) * DMODEL + nx + tx];
    __syncthreads();
    for (int r = ty; r < 32; r += 8)
        T[(size_t)(nx + r) * DMODEL + kx + tx] = __float2half_rn(t[tx][r]);
}

// ---------------------------------------------------------------------------
// kmax (single kernel: block-reduce + one atomicMax per CTA)
// ---------------------------------------------------------------------------
__global__ void kmax_kernel(const float* __restrict__ Kp, unsigned* __restrict__ km)
{
    const int bh = blockIdx.y, sl = blockIdx.x;
    const int b = bh >> 4, h = bh & 15;
    const int tid = threadIdx.x;
    float m = -1e30f;
    const int l0 = sl * 256;
    for (int idx = tid; idx < 256 * MM; idx += 256) {
        int l = l0 + (idx >> 6), mm = idx & 63;
        m = fmaxf(m, Kp[((size_t)(b * LL + l) * HH + h) * MM + mm]);
    }
    __shared__ float red[256];
    red[tid] = m;
    __syncthreads();
    for (int s = 128; s > 0; s >>= 1) {
        if (tid < s) red[tid] = fmaxf(red[tid], red[tid + s]);
        __syncthreads();
    }
    if (tid == 0) atomicMax(&km[bh], fkey(red[0]));
}

// ---------------------------------------------------------------------------
// FAVOR feature map: fp32 in -> fp16 phi out. grid.y: 0=query, 1=key.
// ---------------------------------------------------------------------------
#define FV_P 68
__global__ __launch_bounds__(256)
void favor_kernel(const float* __restrict__ Xq, const float* __restrict__ Xk,
                  __half* __restrict__ Oq, __half* __restrict__ Ok,
                  const float* __restrict__ Wfq, const float* __restrict__ Wfk,
                  const unsigned* __restrict__ kmaxu)
{
    __shared__ float Wt[64 * FV_P];
    __shared__ float xst[64 * FV_P];
    __shared__ float rowss[64];
    __shared__ float rowmx[64];

    const int is_query = (blockIdx.y == 0);
    const float* X = is_query ? Xq : Xk;
    __half* O = is_query ? Oq : Ok;
    const float* Wf = is_query ? Wfq : Wfk;
    const int tid = threadIdx.x;
    const int row0 = blockIdx.x * 64;

    for (int i = tid; i < 64 * 64; i += 256) {
        int d = i >> 6, m = i & 63;
        Wt[m * FV_P + d] = Wf[i];
    }
    {
        const int r = tid >> 2;
        const int m0 = (tid & 3) * 16;
        const float* src = X + (size_t)(row0 + r) * 64 + m0;
#pragma unroll
        for (int j4 = 0; j4 < 4; j4++) {
            float4 v = *(const float4*)(src + j4 * 4);
            int m = m0 + j4 * 4;
            xst[(m + 0) * FV_P + r] = DN * v.x;
            xst[(m + 1) * FV_P + r] = DN * v.y;
            xst[(m + 2) * FV_P + r] = DN * v.z;
            xst[(m + 3) * FV_P + r] = DN * v.w;
        }
    }
    __syncthreads();

    if (tid < 64) {
        float ss = 0.f, mx = -1e30f;
        for (int m = 0; m < 64; m++) {
            float x = xst[m * FV_P + tid];
            ss = fmaf(x, x, ss);
            mx = fmaxf(mx, x);
        }
        rowss[tid] = ss;
        rowmx[tid] = mx;
    }
    __syncthreads();

    const int tx = tid & 15, ty = tid >> 4;
    const int d0 = tx * 4, r0 = ty * 4;
    float acc[4][4];
#pragma unroll
    for (int i = 0; i < 4; i++)
#pragma unroll
        for (int j = 0; j < 4; j++) acc[i][j] = 0.f;

    for (int m = 0; m < 64; m++) {
        float4 w4 = *(float4*)&Wt[m * FV_P + d0];
        float4 x4 = *(float4*)&xst[m * FV_P + r0];
        float wf[4] = {w4.x, w4.y, w4.z, w4.w};
        float xf[4] = {x4.x, x4.y, x4.z, x4.w};
#pragma unroll
        for (int i = 0; i < 4; i++)
#pragma unroll
            for (int j = 0; j < 4; j++)
                acc[i][j] = fmaf(xf[i], wf[j], acc[i][j]);
    }

#pragma unroll
    for (int i = 0; i < 4; i++) {
        const int r = r0 + i;
        const int row = row0 + r;
        float mq;
        if (is_query) mq = rowmx[r];
        else mq = DN * fkey_dec(kmaxu[((row >> 16) << 4) + (row & 15)]);
        const float base = -DIAGC * rowss[r] - mq + 1e-8f;
        __half* dst = O + (size_t)row * 64 + d0;
        *(__half2*)dst = __floats2half2_rn(
            INVSQRTM * fast_exp(acc[i][0] + base),
            INVSQRTM * fast_exp(acc[i][1] + base));
        *(__half2*)(dst + 2) = __floats2half2_rn(
            INVSQRTM * fast_exp(acc[i][2] + base),
            INVSQRTM * fast_exp(acc[i][3] + base));
    }
}

// ---------------------------------------------------------------------------
// chunk_sum (HMMA, trans loads): KV[m][d] = sum_c K[c][m] V[c][d]
// ---------------------------------------------------------------------------
__global__ __launch_bounds__(256)
void chunk_sum_kernel(const __half* __restrict__ Kf, const __half* __restrict__ Vh,
                      float* __restrict__ kv, float* __restrict__ ks)
{
    __shared__ __align__(128) char sK[8192];
    __shared__ __align__(128) char sV[8192];
    const uint32_t kb = smem_to_u32(sK);
    const uint32_t vb = smem_to_u32(sV);

    const int c  = blockIdx.x;
    const int bh = blockIdx.y;
    const int b = bh >> 4, h = bh & 15;
    const int tid = threadIdx.x;
    const int wid = tid >> 5, lid = tid & 31;
    const size_t base = ((size_t)(b * LL + c * CT) * HH + h) * MM;
    const size_t stride = HH * MM;

    {
        const int r = tid >> 2, q16 = (tid & 3) * 32;
        const uint32_t o0 = SWZ128((uint32_t)(r * 128 + q16));
        const uint32_t o1 = SWZ128((uint32_t)(r * 128 + q16 + 16));
        const char* ksrc = (const char*)(Kf + base + (size_t)r * stride) + q16;
        const char* vsrc = (const char*)(Vh + base + (size_t)r * stride) + q16;
        *(uint4*)(sK + o0) = *(const uint4*)ksrc;
        *(uint4*)(sK + o1) = *(const uint4*)(ksrc + 16);
        *(uint4*)(sV + o0) = *(const uint4*)vsrc;
        *(uint4*)(sV + o1) = *(const uint4*)(vsrc + 16);
    }
    __syncthreads();

    const int wm = (wid & 3) * 16;
    const int wn = (wid >> 2) * 32;
    const int a_rc = ((lid >> 4) & 1) * 8 + (lid & 7);
    const int a_mb = wm * 2 + ((lid >> 3) & 1) * 16;
    const int b_rc = ((lid >> 3) & 1) * 8 + (lid & 7);
    const int b_db = (lid >> 4) * 16;

    float acc[4][4];
#pragma unroll
    for (int nt = 0; nt < 4; nt++)
#pragma unroll
        for (int j = 0; j < 4; j++) acc[nt][j] = 0.f;

#pragma unroll
    for (int ksn = 0; ksn < 4; ksn++) {
        const int c0 = ksn * 16;
        uint32_t aa[4], b0[4], b1[4];
        ldsm4t(aa, kb + SWZ128((uint32_t)((c0 + a_rc) * 128 + a_mb)));
        ldsm4t(b0, vb + SWZ128((uint32_t)((c0 + b_rc) * 128 + wn * 2 + b_db)));
        ldsm4t(b1, vb + SWZ128((uint32_t)((c0 + b_rc) * 128 + (wn + 16) * 2 + b_db)));
        mma_f16(acc[0], aa, &b0[0]);
        mma_f16(acc[1], aa, &b0[2]);
        mma_f16(acc[2], aa, &b1[0]);
        mma_f16(acc[3], aa, &b1[2]);
    }

    float* out = kv + (size_t)(bh * NC + c) * MM * MM;
    const int fr = wm + (lid >> 2);
    const int fc = wn + (lid & 3) * 2;
#pragma unroll
    for (int nt = 0; nt < 4; nt++) {
        const int cc = fc + nt * 8;
        float2 lo, hi;
        lo.x = acc[nt][0]; lo.y = acc[nt][1];
        hi.x = acc[nt][2]; hi.y = acc[nt][3];
        *(float2*)&out[fr * 64 + cc] = lo;
        *(float2*)&out[(fr + 8) * 64 + cc] = hi;
    }

    if (tid < 64) {
        float s = 0.f;
        for (int cc = 0; cc < 64; cc++)
            s += __half2float(*(__half*)(sK + SWZ128((uint32_t)(cc * 128 + tid * 2))));
        ks[(size_t)(bh * NC + c) * MM + tid] = s;
    }
}

// ---------------------------------------------------------------------------
// prefix over chunks (4x parallelism): kv(fp32) -> SpH/SpL fp16; ks in place.
// grid (16, NBH), 256 threads; each thread owns one (m,d) element.
// ---------------------------------------------------------------------------
__global__ __launch_bounds__(256)
void prefix_kernel(const float* __restrict__ kv, float* __restrict__ ks,
                   __half* __restrict__ spH, __half* __restrict__ spL)
{
    const int bh = blockIdx.y;
    const int p  = blockIdx.x * 256 + threadIdx.x;   // 0..4095 = m*64+d
    float run = 0.f;
    for (int c = 0; c < NC; c++) {
        const size_t idx = (size_t)(bh * NC + c) * MM * MM + p;
        float val = kv[idx];
        __half hh = __float2half_rn(run);
        spH[idx] = hh;
        spL[idx] = __float2half_rn(run - __half2float(hh));
        run += val;
    }
    if (blockIdx.x == 0 && threadIdx.x < 64) {
        const int m = threadIdx.x;
        float r = 0.f;
        for (int c = 0; c < NC; c++) {
            float* q = ks + (size_t)(bh * NC + c) * MM + m;
            float v = *q;
            *q = r;
            r += v;
        }
    }
}

// ---------------------------------------------------------------------------
// chunk_attn (full HMMA): QK^T -> mask -> As; o = As*V^T + Q*SpH^T + Q*SpL^T
// ---------------------------------------------------------------------------
#define CA_SMEM (49152 + 512)
__global__ __launch_bounds__(256)
void chunk_attn_kernel(const __half* __restrict__ Qf, const __half* __restrict__ Kf,
                       const __half* __restrict__ Vh,
                       const __half* __restrict__ spH, const __half* __restrict__ spL,
                       const float* __restrict__ ksum, __half* __restrict__ Out)
{
    extern __shared__ char smc[];
    const uint32_t sb = smem_to_u32(smc);
    float* zpre = (float*)(smc + 49152);
    float* den  = (float*)(smc + 49152 + 256);

    const int c  = blockIdx.x;
    const int bh = blockIdx.y;
    const int b = bh >> 4, h = bh & 15;
    const int tid = threadIdx.x;
    const int wid = tid >> 5, lid = tid & 31;
    const size_t base = ((size_t)(b * LL + c * CT) * HH + h) * MM;
    const size_t stride = HH * MM;
    const size_t spbase = (size_t)(bh * NC + c) * MM * MM;

    {
        const int r = tid >> 2, q16 = (tid & 3) * 32;
        const uint32_t o0 = SWZ128((uint32_t)(r * 128 + q16));
        const uint32_t o1 = SWZ128((uint32_t)(r * 128 + q16 + 16));
        const char* qsrc = (const char*)(Qf + base + (size_t)r * stride) + q16;
        const char* ksrc = (const char*)(Kf + base + (size_t)r * stride) + q16;
        const char* vsrc = (const char*)(Vh + base + (size_t)r * stride) + q16;
        const char* hsrc = (const char*)(spH + spbase + (size_t)r * 64) + q16;
        const char* lsrc = (const char*)(spL + spbase + (size_t)r * 64) + q16;
        *(uint4*)(smc + o0) = *(const uint4*)qsrc;
        *(uint4*)(smc + o1) = *(const uint4*)(qsrc + 16);
        *(uint4*)(smc + 8192 + o0) = *(const uint4*)ksrc;
        *(uint4*)(smc + 8192 + o1) = *(const uint4*)(ksrc + 16);
        *(uint4*)(smc + 16384 + o0) = *(const uint4*)vsrc;
        *(uint4*)(smc + 16384 + o1) = *(const uint4*)(vsrc + 16);
        *(uint4*)(smc + 32768 + o0) = *(const uint4*)hsrc;
        *(uint4*)(smc + 32768 + o1) = *(const uint4*)(hsrc + 16);
        *(uint4*)(smc + 40960 + o0) = *(const uint4*)lsrc;
        *(uint4*)(smc + 40960 + o1) = *(const uint4*)(lsrc + 16);
    }
    if (tid < 64) {
        zpre[tid] = ksum[(size_t)(bh * NC + c) * MM + tid];
        den[tid] = 0.f;
    }
    __syncthreads();

    const int wm = (wid & 3) * 16;
    const int wn = (wid >> 2) * 32;
    const int a_ro = lid & 15;
    const int a_kb = (lid >> 4) * 16;
    const int b_ro = (lid & 7) + ((lid >> 4) << 3);
    const int b_kb = ((lid >> 3) & 1) * 16;
    const int t_rc = ((lid >> 3) & 1) * 8 + (lid & 7);
    const int t_db = (lid >> 4) * 16;

    float a[4][4];
#pragma unroll
    for (int nt = 0; nt < 4; nt++)
#pragma unroll
        for (int j = 0; j < 4; j++) a[nt][j] = 0.f;
#pragma unroll
    for (int ksn = 0; ksn < 4; ksn++) {
        const int kb = ksn * 32;
        uint32_t aa[4], b0[4], b1[4];
        ldsm4(aa, sb + SWZ128((uint32_t)((wm + a_ro) * 128 + kb + a_kb)));
        ldsm4(b0, sb + 8192 + SWZ128((uint32_t)((wn + b_ro) * 128 + kb + b_kb)));
        ldsm4(b1, sb + 8192 + SWZ128((uint32_t)((wn + 16 + b_ro) * 128 + kb + b_kb)));
        mma_f16(a[0], aa, &b0[0]);
        mma_f16(a[1], aa, &b0[2]);
        mma_f16(a[2], aa, &b1[0]);
        mma_f16(a[3], aa, &b1[2]);
    }
    const int fr = wm + (lid >> 2);
    const int fcb = wn + (lid & 3) * 2;
    {
        float rs_lo = 0.f, rs_hi = 0.f;
#pragma unroll
        for (int nt = 0; nt < 4; nt++) {
            const int c0 = fcb + nt * 8;
            float v00 = (c0     <= fr)     ? a[nt][0] : 0.f;
            float v01 = (c0 + 1 <= fr)     ? a[nt][1] : 0.f;
            float v10 = (c0     <= fr + 8) ? a[nt][2] : 0.f;
            float v11 = (c0 + 1 <= fr + 8) ? a[nt][3] : 0.f;
            rs_lo += v00 + v01;
            rs_hi += v10 + v11;
            *(__half2*)(smc + 24576 + SWZ128((uint32_t)(fr * 128 + c0 * 2))) =
                __floats2half2_rn(v00, v01);
            *(__half2*)(smc + 24576 + SWZ128((uint32_t)((fr + 8) * 128 + c0 * 2))) =
                __floats2half2_rn(v10, v11);
        }
        atomicAdd(&den[fr], rs_lo);
        atomicAdd(&den[fr + 8], rs_hi);
    }
    __syncthreads();

    float o[4][4];
#pragma unroll
    for (int nt = 0; nt < 4; nt++)
#pragma unroll
        for (int j = 0; j < 4; j++) o[nt][j] = 0.f;
#pragma unroll
    for (int ksn = 0; ksn < 4; ksn++) {
        const int kb = ksn * 32;
        const int k0 = ksn * 16;
        uint32_t aA[4], aQ[4], bv0[4], bv1[4], bh0[4], bh1[4], bl0[4], bl1[4];
        ldsm4(aA, sb + 24576 + SWZ128((uint32_t)((wm + a_ro) * 128 + kb + a_kb)));
        ldsm4(aQ, sb + SWZ128((uint32_t)((wm + a_ro) * 128 + kb + a_kb)));
        ldsm4t(bv0, sb + 16384 + SWZ128((uint32_t)((k0 + t_rc) * 128 + wn * 2 + t_db)));
        ldsm4t(bv1, sb + 16384 + SWZ128((uint32_t)((k0 + t_rc) * 128 + (wn + 16) * 2 + t_db)));
        ldsm4t(bh0, sb + 32768 + SWZ128((uint32_t)((k0 + t_rc) * 128 + wn * 2 + t_db)));
        ldsm4t(bh1, sb + 32768 + SWZ128((uint32_t)((k0 + t_rc) * 128 + (wn + 16) * 2 + t_db)));
        ldsm4t(bl0, sb + 40960 + SWZ128((uint32_t)((k0 + t_rc) * 128 + wn * 2 + t_db)));
        ldsm4t(bl1, sb + 40960 + SWZ128((uint32_t)((k0 + t_rc) * 128 + (wn + 16) * 2 + t_db)));
        mma_f16(o[0], aA, &bv0[0]); mma_f16(o[1], aA, &bv0[2]);
        mma_f16(o[2], aA, &bv1[0]); mma_f16(o[3], aA, &bv1[2]);
        mma_f16(o[0], aQ, &bh0[0]); mma_f16(o[1], aQ, &bh0[2]);
        mma_f16(o[2], aQ, &bh1[0]); mma_f16(o[3], aQ, &bh1[2]);
        mma_f16(o[0], aQ, &bl0[0]); mma_f16(o[1], aQ, &bl0[2]);
        mma_f16(o[2], aQ, &bl1[0]); mma_f16(o[3], aQ, &bl1[2]);
    }

    if (tid < 64) {
        float s = den[tid];
        for (int m = 0; m < 64; m++)
            s = fmaf(__half2float(*(__half*)(smc + SWZ128((uint32_t)(tid * 128 + m * 2)))),
                     zpre[m], s);
        den[tid] = s;
    }
    __syncthreads();

    const float d0inv = 1.f / den[fr];
    const float d1inv = 1.f / den[fr + 8];
#pragma unroll
    for (int nt = 0; nt < 4; nt++) {
        const int c0 = fcb + nt * 8;
        *(__half2*)&Out[base + (size_t)fr * stride + c0] =
            __floats2half2_rn(o[nt][0] * d0inv, o[nt][1] * d0inv);
        *(__half2*)&Out[base + (size_t)(fr + 8) * stride + c0] =
            __floats2half2_rn(o[nt][2] * d1inv, o[nt][3] * d1inv);
    }
}

// ---------------------------------------------------------------------------
// Launch
// ---------------------------------------------------------------------------
extern "C" void kernel_launch(void* const* d_in, const int* in_sizes, int n_in,
                              void* d_out, int out_size)
{
    const float* queries = (const float*)d_in[0];
    const float* keys    = (const float*)d_in[1];
    const float* values  = (const float*)d_in[2];
    const float* Wq = (const float*)d_in[3];
    const float* bq = (const float*)d_in[4];
    const float* Wk = (const float*)d_in[5];
    const float* bk = (const float*)d_in[6];
    const float* Wv = (const float*)d_in[7];
    const float* bv = (const float*)d_in[8];
    const float* Wo = (const float*)d_in[9];
    const float* bo = (const float*)d_in[10];
    const float* Wfq = (const float*)d_in[11];
    const float* Wfk = (const float*)d_in[12];
    float* out = (float*)d_out;

    float *gq, *gk, *gkv, *gks;
    unsigned* gkm;
    __half *gxh, *gvh, *gqf, *gkf, *goh, *gwh, *gsph, *gspl;
    cudaGetSymbolAddress((void**)&gq, g_q);
    cudaGetSymbolAddress((void**)&gk, g_k);
    cudaGetSymbolAddress((void**)&gkm, g_kmax_u);
    cudaGetSymbolAddress((void**)&gkv, g_kv);
    cudaGetSymbolAddress((void**)&gks, g_ks);
    cudaGetSymbolAddress((void**)&gxh, g_xh);
    cudaGetSymbolAddress((void**)&gvh, g_vh);
    cudaGetSymbolAddress((void**)&gqf, g_qf);
    cudaGetSymbolAddress((void**)&gkf, g_kf);
    cudaGetSymbolAddress((void**)&goh, g_oh);
    cudaGetSymbolAddress((void**)&gwh, g_wh);
    cudaGetSymbolAddress((void**)&gsph, g_sph);
    cudaGetSymbolAddress((void**)&gspl, g_spl);

    const size_t WSZ = (size_t)DMODEL * DMODEL;
    const size_t XSZ = (size_t)MROWS * DMODEL;

    cudaMemsetAsync(gkm, 0, NBH * sizeof(unsigned));

    WtBatch wb;
    wb.W[0] = Wq; wb.W[1] = Wk; wb.W[2] = Wv; wb.W[3] = Wo;
    for (int i = 0; i < 4; i++) wb.T[i] = gwh + i * WSZ;
    wt_cvt_kernel<<<dim3(32, 32, 4), 256>>>(wb);

    CvtBatch cb;
    cb.x[0] = queries; cb.x[1] = keys; cb.x[2] = values;
    for (int i = 0; i < 3; i++) cb.h[i] = gxh + i * XSZ;
    cvt_f16_kernel<<<dim3((int)(XSZ / 1024), 3), 256>>>(cb);

    cudaFuncSetAttribute(gemm_f16, cudaFuncAttributeMaxDynamicSharedMemorySize, GM_SMEM);
    GemmBatch gb;
    for (int i = 0; i < 3; i++) {
        gb.A[i] = gxh + i * XSZ;
        gb.B[i] = gwh + i * WSZ;
    }
    gb.bias[0] = bq; gb.bias[1] = bk; gb.bias[2] = bv;
    gb.C[0] = gq; gb.C[1] = gk; gb.C[2] = gvh;
    gb.hout[0] = 0; gb.hout[1] = 0; gb.hout[2] = 1;
    gemm_f16<<<dim3(DMODEL / 128, MROWS / 128, 3), 256, GM_SMEM>>>(gb);

    kmax_kernel<<<dim3(16, NBH), 256>>>(gk, gkm);

    favor_kernel<<<dim3(NROWS / 64, 2), 256>>>(gq, gk, gqf, gkf, Wfq, Wfk, gkm);

    chunk_sum_kernel<<<dim3(NC, NBH), 256>>>(gkf, gvh, gkv, gks);
    prefix_kernel<<<dim3(16, NBH), 256>>>(gkv, gks, gsph, gspl);

    cudaFuncSetAttribute(chunk_attn_kernel,
                         cudaFuncAttributeMaxDynamicSharedMemorySize, CA_SMEM);
    chunk_attn_kernel<<<dim3(NC, NBH), 256, CA_SMEM>>>(gqf, gkf, gvh, gsph, gspl, gks, goh);

    GemmBatch ob;
    ob.A[0] = goh; ob.B[0] = gwh + 3 * WSZ; ob.bias[0] = bo;
    ob.C[0] = out; ob.hout[0] = 0;
    for (int i = 1; i < 3; i++) {
        ob.A[i] = goh; ob.B[i] = ob.B[0]; ob.bias[i] = bo;
        ob.C[i] = out; ob.hout[i] = 0;
    }
    gemm_f16<<<dim3(DMODEL / 128, MROWS / 128, 1), 256, GM_SMEM>>>(ob);
}